// round 2
// baseline (speedup 1.0000x reference)
#include <cuda_runtime.h>
#include <mma.h>
#include <math.h>

using namespace nvcuda;

#define NB   32
#define LK   4096
#define DM   512
#define NH   8
#define DH   64
#define DFF  2048
#define LQ   22
#define SKK  45
#define NTOP 20
#define ROWS 176
#define RPAD 192

// ---------------- scratch ----------------
__device__ float g_q[LQ * DM];
__device__ float g_qw[RPAD * DM];                 // rows >=176 stay zero
__device__ unsigned char g_istop[NB * ROWS];
__device__ float g_S[(size_t)NB * RPAD * LK];     // scaled logits, 402 MB
__device__ float g_pmax[NB * RPAD * 32];
__device__ float g_psum[NB * RPAD * 32];
__device__ float g_rmax[NB * RPAD];
__device__ float g_rinv[NB * RPAD];
__device__ float g_encsum[NB * DM];
__device__ float g_u[2 * (size_t)NB * RPAD * DM]; // split-K halves
__device__ float g_ctx[NB * LQ * DM];
__device__ float g_x[NB * LQ * DM];
__device__ float g_ff[(size_t)NB * LQ * DFF];
__device__ float g_z[NB * LQ * DM];

// ---------------- helpers ----------------
__device__ __forceinline__ float blockReduce(float v, float* red) {
    __syncthreads();
    #pragma unroll
    for (int o = 16; o; o >>= 1) v += __shfl_down_sync(0xffffffffu, v, o);
    int w = threadIdx.x >> 5;
    if ((threadIdx.x & 31) == 0) red[w] = v;
    __syncthreads();
    if (threadIdx.x < 32) {
        float x = (threadIdx.x < (blockDim.x >> 5)) ? red[threadIdx.x] : 0.f;
        #pragma unroll
        for (int o = 16; o; o >>= 1) x += __shfl_down_sync(0xffffffffu, x, o);
        if (threadIdx.x == 0) red[0] = x;
    }
    __syncthreads();
    return red[0];
}

// ---------------- zero encsum ----------------
__global__ void zero_kernel() {
    int i = blockIdx.x * 256 + threadIdx.x;
    if (i < NB * DM) g_encsum[i] = 0.f;
}

// ---------------- q = pe @ Wq + bq ----------------
__global__ void q_kernel(const float* __restrict__ Wq, const float* __restrict__ bq) {
    int l = blockIdx.x, t = threadIdx.x;
    __shared__ float spe[DM];
    const float c = logf(10000.0f) / 512.0f;
    for (int j = t; j < DM; j += 256) {
        int i = j >> 1;
        float arg = (float)l * expf(-(float)(2 * i) * c);
        spe[j] = (j & 1) ? cosf(arg) : sinf(arg);
    }
    __syncthreads();
    for (int n = t; n < DM; n += 256) {
        float a = bq[n];
        for (int k = 0; k < DM; k++) a += spe[k] * Wq[k * DM + n];
        g_q[l * DM + n] = a;
    }
}

// ---------------- qW[row,c] = sum_d q[q, h64+d] * Wk[c, h64+d] ----------------
__global__ void qw_kernel(const float* __restrict__ Wk) {
    int row = blockIdx.x, h = row / LQ, q = row % LQ, t = threadIdx.x;
    __shared__ float sq[64];
    if (t < 64) sq[t] = g_q[q * DM + h * 64 + t];
    __syncthreads();
    for (int c = t; c < DM; c += 256) {
        const float* wr = Wk + (size_t)c * DM + h * 64;
        float a = 0.f;
        #pragma unroll
        for (int d = 0; d < 64; d++) a += sq[d] * wr[d];
        g_qw[row * DM + c] = a;
    }
}

// ---------------- sampled scores + M + stable top-20 mask (pure fp32) --------
__global__ void samp_kernel(const float* __restrict__ enc) {
    extern __shared__ float sm[];
    float* se = sm;                 // [45][512]
    float* sc = sm + SKK * DM;      // [176][45]
    float* sM = sc + ROWS * SKK;    // [176]
    int b = blockIdx.x, t = threadIdx.x;
    for (int i = t; i < SKK * DM; i += 256) {
        int s = i / DM, c = i % DM;
        int l = (s * LK) / SKK;
        se[i] = enc[((size_t)b * LK + l) * DM + c];
    }
    __syncthreads();
    for (int i = t; i < ROWS * SKK; i += 256) {
        int row = i / SKK, s = i % SKK;
        const float* qw = g_qw + row * DM;
        const float* e = se + s * DM;
        float a = 0.f;
        for (int c = 0; c < DM; c++) a += qw[c] * e[c];
        sc[i] = a;
    }
    __syncthreads();
    if (t < ROWS) {
        float mx = -1e30f, su = 0.f;
        for (int s = 0; s < SKK; s++) { float v = sc[t * SKK + s]; mx = fmaxf(mx, v); su += v; }
        sM[t] = mx - su * (1.0f / SKK);
    }
    __syncthreads();
    if (t < ROWS) {
        int h = t / LQ, q = t % LQ, base = h * LQ, rank = 0;
        float mv = sM[t];
        for (int i = 0; i < LQ; i++) {
            float o = sM[base + i];
            rank += (o > mv) || (o == mv && i < q);
        }
        g_istop[b * ROWS + t] = (rank < NTOP) ? 1 : 0;
    }
}

// ---------------- S GEMM: S = 0.125 * qW @ enc^T, with partial softmax stats -
// block: 96 rows x 128 l, K=512. grid (32 nt, 2 mt, 32 b). 8 warps = 2m x 4n.
__global__ void __launch_bounds__(256) s_gemm(const float* __restrict__ enc) {
    extern __shared__ float smd[];
    float* As = smd;            // [96][36]
    float* Bs = smd + 96 * 36;  // [128][36]  enc tile [l][c]
    int t = threadIdx.x, warp = t >> 5;
    int nt = blockIdx.x, mt = blockIdx.y, b = blockIdx.z;
    int m0 = mt * 96, n0 = nt * 128;
    int wm = warp >> 2, wn = warp & 3;

    wmma::fragment<wmma::accumulator, 16, 16, 8, float> acc[3][2];
    #pragma unroll
    for (int i = 0; i < 3; i++)
        #pragma unroll
        for (int j = 0; j < 2; j++) wmma::fill_fragment(acc[i][j], 0.0f);

    for (int k0 = 0; k0 < DM; k0 += 32) {
        #pragma unroll
        for (int i4 = t; i4 < 768; i4 += 256) {
            int r = i4 >> 3, c4 = (i4 & 7) * 4;
            *(float4*)(As + r * 36 + c4) = *(const float4*)(g_qw + (m0 + r) * DM + k0 + c4);
        }
        #pragma unroll
        for (int i4 = t; i4 < 1024; i4 += 256) {
            int l = i4 >> 3, c4 = (i4 & 7) * 4;
            *(float4*)(Bs + l * 36 + c4) =
                *(const float4*)(enc + ((size_t)b * LK + n0 + l) * DM + k0 + c4);
        }
        __syncthreads();
        if (mt == 0) {  // fused enc column sums (for v-mean)
            int c = t >> 3, g = t & 7;
            float v = 0.f;
            for (int l = g * 16; l < g * 16 + 16; l++) v += Bs[l * 36 + c];
            #pragma unroll
            for (int o = 4; o; o >>= 1) v += __shfl_down_sync(0xffffffffu, v, o);
            if (g == 0) atomicAdd(&g_encsum[b * DM + k0 + c], v);
        }
        #pragma unroll
        for (int kk = 0; kk < 4; kk++) {
            wmma::fragment<wmma::matrix_a, 16, 16, 8, wmma::precision::tf32, wmma::row_major> af[3];
            wmma::fragment<wmma::matrix_b, 16, 16, 8, wmma::precision::tf32, wmma::col_major> bf[2];
            #pragma unroll
            for (int i = 0; i < 3; i++) {
                wmma::load_matrix_sync(af[i], As + (wm * 48 + i * 16) * 36 + kk * 8, 36);
                #pragma unroll
                for (int e = 0; e < af[i].num_elements; e++) af[i].x[e] = wmma::__float_to_tf32(af[i].x[e]);
            }
            #pragma unroll
            for (int j = 0; j < 2; j++) {
                wmma::load_matrix_sync(bf[j], Bs + (wn * 32 + j * 16) * 36 + kk * 8, 36);
                #pragma unroll
                for (int e = 0; e < bf[j].num_elements; e++) bf[j].x[e] = wmma::__float_to_tf32(bf[j].x[e]);
            }
            #pragma unroll
            for (int i = 0; i < 3; i++)
                #pragma unroll
                for (int j = 0; j < 2; j++) wmma::mma_sync(acc[i][j], af[i], bf[j], acc[i][j]);
        }
        __syncthreads();
    }
    float* Ss = smd;  // [96][132] staging (aliases As/Bs, safe after sync)
    #pragma unroll
    for (int i = 0; i < 3; i++)
        #pragma unroll
        for (int j = 0; j < 2; j++)
            wmma::store_matrix_sync(Ss + (wm * 48 + i * 16) * 132 + wn * 32 + j * 16,
                                    acc[i][j], 132, wmma::mem_row_major);
    __syncthreads();
    const float scale = 0.125f;
    size_t base = ((size_t)b * RPAD + m0) * LK + n0;
    for (int i4 = t; i4 < 3072; i4 += 256) {
        int r = i4 >> 5, c4 = (i4 & 31) * 4;
        float4 v = *(float4*)(Ss + r * 132 + c4);
        v.x *= scale; v.y *= scale; v.z *= scale; v.w *= scale;
        *(float4*)(Ss + r * 132 + c4) = v;
        *(float4*)(g_S + base + (size_t)r * LK + c4) = v;
    }
    __syncthreads();
    if (t < 96) {
        float mx = -1e30f;
        for (int c = 0; c < 128; c++) mx = fmaxf(mx, Ss[t * 132 + c]);
        float su = 0.f;
        for (int c = 0; c < 128; c++) su += __expf(Ss[t * 132 + c] - mx);
        int rr = b * RPAD + m0 + t;
        g_pmax[rr * 32 + nt] = mx;
        g_psum[rr * 32 + nt] = su;
    }
}

// ---------------- merge softmax stats (log-sum-exp) ----------------
__global__ void stat_merge() {
    int r = blockIdx.x * 256 + threadIdx.x;
    if (r >= NB * RPAD) return;
    float m = -1e30f;
    for (int i = 0; i < 32; i++) m = fmaxf(m, g_pmax[r * 32 + i]);
    float s = 0.f;
    for (int i = 0; i < 32; i++) s += g_psum[r * 32 + i] * __expf(g_pmax[r * 32 + i] - m);
    g_rmax[r] = m;
    g_rinv[r] = 1.0f / s;
}

// ---------------- u GEMM: u = P @ enc (P formed on the fly) ----------------
// block: 96 rows x 256 c, split-K (2 halves of 2048). 8 warps = 2m x 4n.
__global__ void __launch_bounds__(256) u_gemm(const float* __restrict__ enc) {
    __shared__ __align__(16) float As[96 * 36];
    __shared__ __align__(16) float Bs[32 * 260];
    __shared__ float smx[96], sri[96];
    int t = threadIdx.x, warp = t >> 5;
    int gx = blockIdx.x, b = blockIdx.y;
    int nt = gx & 1, mt = (gx >> 1) & 1, kc = gx >> 2;
    int m0 = mt * 96, n0 = nt * 256;
    int wm = warp >> 2, wn = warp & 3;
    if (t < 96) { int rr = b * RPAD + m0 + t; smx[t] = g_rmax[rr]; sri[t] = g_rinv[rr]; }
    __syncthreads();

    wmma::fragment<wmma::accumulator, 16, 16, 8, float> acc[3][4];
    #pragma unroll
    for (int i = 0; i < 3; i++)
        #pragma unroll
        for (int j = 0; j < 4; j++) wmma::fill_fragment(acc[i][j], 0.0f);

    for (int k0 = kc * 2048; k0 < kc * 2048 + 2048; k0 += 32) {
        #pragma unroll
        for (int i4 = t; i4 < 768; i4 += 256) {
            int r = i4 >> 3, c0 = (i4 & 7) * 4;
            float4 s = *(const float4*)(g_S + ((size_t)b * RPAD + m0 + r) * LK + k0 + c0);
            float m = smx[r], ri = sri[r];
            float4 p;
            p.x = __expf(s.x - m) * ri;
            p.y = __expf(s.y - m) * ri;
            p.z = __expf(s.z - m) * ri;
            p.w = __expf(s.w - m) * ri;
            *(float4*)(As + r * 36 + c0) = p;
        }
        #pragma unroll
        for (int i4 = t; i4 < 2048; i4 += 256) {
            int l = i4 >> 6, c4 = (i4 & 63) * 4;
            *(float4*)(Bs + l * 260 + c4) =
                *(const float4*)(enc + ((size_t)b * LK + k0 + l) * DM + n0 + c4);
        }
        __syncthreads();
        #pragma unroll
        for (int kk = 0; kk < 4; kk++) {
            wmma::fragment<wmma::matrix_a, 16, 16, 8, wmma::precision::tf32, wmma::row_major> af[3];
            wmma::fragment<wmma::matrix_b, 16, 16, 8, wmma::precision::tf32, wmma::row_major> bf[4];
            #pragma unroll
            for (int i = 0; i < 3; i++) {
                wmma::load_matrix_sync(af[i], As + (wm * 48 + i * 16) * 36 + kk * 8, 36);
                #pragma unroll
                for (int e = 0; e < af[i].num_elements; e++) af[i].x[e] = wmma::__float_to_tf32(af[i].x[e]);
            }
            #pragma unroll
            for (int j = 0; j < 4; j++) {
                wmma::load_matrix_sync(bf[j], Bs + (kk * 8) * 260 + wn * 64 + j * 16, 260);
                #pragma unroll
                for (int e = 0; e < bf[j].num_elements; e++) bf[j].x[e] = wmma::__float_to_tf32(bf[j].x[e]);
            }
            #pragma unroll
            for (int i = 0; i < 3; i++)
                #pragma unroll
                for (int j = 0; j < 4; j++) wmma::mma_sync(acc[i][j], af[i], bf[j], acc[i][j]);
        }
        __syncthreads();
    }
    float* up = g_u + (size_t)kc * NB * RPAD * DM;
    #pragma unroll
    for (int i = 0; i < 3; i++)
        #pragma unroll
        for (int j = 0; j < 4; j++)
            wmma::store_matrix_sync(up + ((size_t)(b * RPAD + m0 + wm * 48 + i * 16)) * DM
                                       + n0 + wn * 64 + j * 16,
                                    acc[i][j], DM, wmma::mem_row_major);
}

// ---------------- ctx: top rows u@Wv_h + bv, else v-mean ----------------
__global__ void ctx_kernel(const float* __restrict__ Wv, const float* __restrict__ bv) {
    __shared__ float su[LQ * DM];
    __shared__ float svm[64];
    int bh = blockIdx.x, b = bh >> 3, h = bh & 7, t = threadIdx.x;
    const size_t ub = ((size_t)b * RPAD + h * LQ) * DM;
    const size_t half = (size_t)NB * RPAD * DM;
    for (int i = t; i < LQ * DM; i += 256) su[i] = g_u[ub + i] + g_u[half + ub + i];
    if (t < 64) {
        float a = bv[h * 64 + t];
        const float inv = 1.0f / 4096.f;
        for (int c = 0; c < DM; c++) a += g_encsum[b * DM + c] * inv * Wv[c * DM + h * 64 + t];
        svm[t] = a;
    }
    __syncthreads();
    for (int i = t; i < LQ * 64; i += 256) {
        int q = i >> 6, d = i & 63;
        float v;
        if (g_istop[b * ROWS + h * LQ + q]) {
            float a = bv[h * 64 + d];
            for (int c = 0; c < DM; c++) a += su[q * DM + c] * Wv[c * DM + h * 64 + d];
            v = a;
        } else v = svm[d];
        g_ctx[((size_t)b * LQ + q) * DM + h * 64 + d] = v;
    }
}

// ---------------- f1: x = LN(2*(ctx@Wo+bo)) ----------------
__global__ void f1_kernel(const float* __restrict__ Wo, const float* __restrict__ bo,
                          const float* __restrict__ g1, const float* __restrict__ be1) {
    int r = blockIdx.x, t = threadIdx.x;
    __shared__ float sc[DM];
    __shared__ float red[32];
    for (int j = t; j < DM; j += 256) sc[j] = g_ctx[(size_t)r * DM + j];
    __syncthreads();
    float z[2];
    #pragma unroll
    for (int u2 = 0; u2 < 2; u2++) {
        int n = t + u2 * 256;
        float a = bo[n];
        for (int k = 0; k < DM; k++) a += sc[k] * Wo[k * DM + n];
        z[u2] = 2.0f * a;
    }
    float s1 = blockReduce(z[0] + z[1], red);
    float s2 = blockReduce(z[0] * z[0] + z[1] * z[1], red);
    float mu = s1 * (1.0f / 512.f);
    float va = fmaxf(s2 * (1.0f / 512.f) - mu * mu, 0.f);
    float rs = rsqrtf(va + 1e-5f);
    #pragma unroll
    for (int u2 = 0; u2 < 2; u2++) {
        int n = t + u2 * 256;
        g_x[(size_t)r * DM + n] = (z[u2] - mu) * rs * g1[n] + be1[n];
    }
}

// ---------------- f2: ff = relu(x @ W1^T + b1) ----------------
__global__ void __launch_bounds__(256) f2_kernel(const float* __restrict__ w1,
                                                 const float* __restrict__ b1) {
    __shared__ float sx[LQ * DM];
    int b = blockIdx.x, t = threadIdx.x;
    for (int i = t; i < LQ * DM; i += 256) sx[i] = g_x[(size_t)b * LQ * DM + i];
    __syncthreads();
    for (int j = t; j < DFF; j += 256) {
        float acc[LQ];
        float bj = b1[j];
        #pragma unroll
        for (int q = 0; q < LQ; q++) acc[q] = bj;
        const float4* wr = (const float4*)(w1 + (size_t)j * DM);
        for (int c4 = 0; c4 < DM / 4; c4++) {
            float4 w = wr[c4];
            #pragma unroll
            for (int q = 0; q < LQ; q++) {
                const float* xr = sx + q * DM + c4 * 4;
                acc[q] += xr[0] * w.x + xr[1] * w.y + xr[2] * w.z + xr[3] * w.w;
            }
        }
        #pragma unroll
        for (int q = 0; q < LQ; q++)
            g_ff[((size_t)b * LQ + q) * DFF + j] = fmaxf(acc[q], 0.f);
    }
}

// ---------------- f3a: z = x + ff @ W2^T + b2 ----------------
__global__ void __launch_bounds__(256) f3a_kernel(const float* __restrict__ w2,
                                                  const float* __restrict__ b2) {
    extern __shared__ float sff[];  // [22][2048]
    int b = blockIdx.x, t = threadIdx.x;
    for (int i = t; i < LQ * DFF; i += 256) sff[i] = g_ff[(size_t)b * LQ * DFF + i];
    __syncthreads();
    for (int j = t; j < DM; j += 256) {
        float acc[LQ];
        float bj = b2[j];
        #pragma unroll
        for (int q = 0; q < LQ; q++) acc[q] = bj;
        const float4* wr = (const float4*)(w2 + (size_t)j * DFF);
        for (int c4 = 0; c4 < DFF / 4; c4++) {
            float4 w = wr[c4];
            #pragma unroll
            for (int q = 0; q < LQ; q++) {
                const float* fr = sff + q * DFF + c4 * 4;
                acc[q] += fr[0] * w.x + fr[1] * w.y + fr[2] * w.z + fr[3] * w.w;
            }
        }
        #pragma unroll
        for (int q = 0; q < LQ; q++) {
            size_t o = ((size_t)b * LQ + q) * DM + j;
            g_z[o] = g_x[o] + acc[q];
        }
    }
}

// ---------------- f3b: y = LN(z); forecast = y@Wout + bout ----------------
__global__ void f3b_kernel(const float* __restrict__ g2, const float* __restrict__ be2,
                           const float* __restrict__ Wout, const float* __restrict__ bout,
                           float* __restrict__ out) {
    int r = blockIdx.x, t = threadIdx.x;
    __shared__ float red[32];
    float z0 = g_z[(size_t)r * DM + t];
    float z1 = g_z[(size_t)r * DM + t + 256];
    float s1 = blockReduce(z0 + z1, red);
    float s2 = blockReduce(z0 * z0 + z1 * z1, red);
    float mu = s1 * (1.0f / 512.f);
    float va = fmaxf(s2 * (1.0f / 512.f) - mu * mu, 0.f);
    float rs = rsqrtf(va + 1e-5f);
    float y0 = (z0 - mu) * rs * g2[t] + be2[t];
    float y1 = (z1 - mu) * rs * g2[t + 256] + be2[t + 256];
    out[NB * LQ + (size_t)r * DM + t] = y0;
    out[NB * LQ + (size_t)r * DM + t + 256] = y1;
    float f = blockReduce(y0 * Wout[t] + y1 * Wout[t + 256], red);
    if (t == 0) out[r] = f + bout[0];
}

// ---------------- launch ----------------
extern "C" void kernel_launch(void* const* d_in, const int* in_sizes, int n_in,
                              void* d_out, int out_size) {
    const float* enc  = (const float*)d_in[0];
    const float* Wq   = (const float*)d_in[1];
    const float* bq   = (const float*)d_in[2];
    const float* Wk   = (const float*)d_in[3];
    const float* Wv   = (const float*)d_in[5];
    const float* bv   = (const float*)d_in[6];
    const float* Wo   = (const float*)d_in[7];
    const float* bo   = (const float*)d_in[8];
    const float* w1   = (const float*)d_in[9];
    const float* b1   = (const float*)d_in[10];
    const float* w2   = (const float*)d_in[11];
    const float* b2   = (const float*)d_in[12];
    const float* g1   = (const float*)d_in[13];
    const float* be1  = (const float*)d_in[14];
    const float* g2   = (const float*)d_in[15];
    const float* be2  = (const float*)d_in[16];
    const float* Wout = (const float*)d_in[17];
    const float* bout = (const float*)d_in[18];
    float* out = (float*)d_out;

    cudaFuncSetAttribute(samp_kernel, cudaFuncAttributeMaxDynamicSharedMemorySize, 126976);
    cudaFuncSetAttribute(s_gemm,      cudaFuncAttributeMaxDynamicSharedMemorySize, 53248);
    cudaFuncSetAttribute(f3a_kernel,  cudaFuncAttributeMaxDynamicSharedMemorySize, 184320);

    zero_kernel<<<64, 256>>>();
    q_kernel<<<22, 256>>>(Wq, bq);
    qw_kernel<<<176, 256>>>(Wk);
    samp_kernel<<<32, 256, 124544>>>(enc);
    dim3 gc(32, 2, NB);
    s_gemm<<<gc, 256, 50688>>>(enc);
    stat_merge<<<24, 256>>>();
    dim3 ge(8, NB);
    u_gemm<<<ge, 256>>>(enc);
    ctx_kernel<<<256, 256>>>(Wv, bv);
    f1_kernel<<<NB * LQ, 256>>>(Wo, bo, g1, be1);
    f2_kernel<<<NB, 256>>>(w1, b1);
    f3a_kernel<<<NB, 256, 180224>>>(w2, b2);
    f3b_kernel<<<NB * LQ, 256>>>(g2, be2, Wout, bout, out);
}

// round 3
// speedup vs baseline: 1.8519x; 1.8519x over previous
#include <cuda_runtime.h>
#include <mma.h>
#include <math.h>

using namespace nvcuda;

#define NB   32
#define LK   4096
#define DM   512
#define NH   8
#define DH   64
#define DFF  2048
#define LQ   22
#define SKK  45
#define NTOP 20
#define ROWS 176
#define RPAD 192
#define MROWS (NB * LQ)      // 704
#define MPAD  768

// ---------------- scratch (zero-initialized device globals) ----------------
__device__ float g_q[LQ * DM];
__device__ float g_qw[RPAD * DM];                 // rows >=176 stay zero
__device__ float g_sc[NB * ROWS * 48];
__device__ unsigned char g_istop[NB * ROWS];
__device__ float g_S[(size_t)NB * RPAD * LK];     // scaled logits
__device__ float g_pmax[NB * RPAD * 32];
__device__ float g_psum[NB * RPAD * 32];
__device__ float g_rmax[NB * RPAD];
__device__ float g_rinv[NB * RPAD];
__device__ float g_encsum[NB * DM];
__device__ float g_u[2 * (size_t)NB * RPAD * DM]; // split-K halves
__device__ float g_ctx[NB * LQ * DM];
__device__ float g_x[MPAD * DM];                  // rows >=704 stay zero
__device__ float g_ff[(size_t)MPAD * DFF];
__device__ float g_z[MROWS * DM];

// ---------------- helpers ----------------
__device__ __forceinline__ float blockReduce(float v, float* red) {
    __syncthreads();
    #pragma unroll
    for (int o = 16; o; o >>= 1) v += __shfl_down_sync(0xffffffffu, v, o);
    int w = threadIdx.x >> 5;
    if ((threadIdx.x & 31) == 0) red[w] = v;
    __syncthreads();
    if (threadIdx.x < 32) {
        float x = (threadIdx.x < (blockDim.x >> 5)) ? red[threadIdx.x] : 0.f;
        #pragma unroll
        for (int o = 16; o; o >>= 1) x += __shfl_down_sync(0xffffffffu, x, o);
        if (threadIdx.x == 0) red[0] = x;
    }
    __syncthreads();
    return red[0];
}

// ---------------- zero encsum ----------------
__global__ void zero_kernel() {
    int i = blockIdx.x * 256 + threadIdx.x;
    if (i < NB * DM) g_encsum[i] = 0.f;
}

// ---------------- q = pe @ Wq + bq ----------------
__global__ void q_kernel(const float* __restrict__ Wq, const float* __restrict__ bq) {
    int l = blockIdx.x, t = threadIdx.x;
    __shared__ float spe[DM];
    const float c = logf(10000.0f) / 512.0f;
    for (int j = t; j < DM; j += 256) {
        int i = j >> 1;
        float arg = (float)l * expf(-(float)(2 * i) * c);
        spe[j] = (j & 1) ? cosf(arg) : sinf(arg);
    }
    __syncthreads();
    for (int n = t; n < DM; n += 256) {
        float a = bq[n];
        for (int k = 0; k < DM; k++) a += spe[k] * Wq[k * DM + n];
        g_q[l * DM + n] = a;
    }
}

// ---------------- qW[row,c] = sum_d q[q, h64+d] * Wk[c, h64+d] ----------------
__global__ void qw_kernel(const float* __restrict__ Wk) {
    int row = blockIdx.x, h = row / LQ, q = row % LQ, t = threadIdx.x;
    __shared__ float sq[64];
    if (t < 64) sq[t] = g_q[q * DM + h * 64 + t];
    __syncthreads();
    for (int c = t; c < DM; c += 256) {
        const float* wr = Wk + (size_t)c * DM + h * 64;
        float a = 0.f;
        #pragma unroll
        for (int d = 0; d < 64; d++) a += sq[d] * wr[d];
        g_qw[row * DM + c] = a;
    }
}

// ---------------- sampled scores: grid (NB*SKK), warp-per-row dots ----------
__global__ void __launch_bounds__(256) samp_score(const float* __restrict__ enc) {
    int b = blockIdx.x / SKK, s = blockIdx.x % SKK;
    int t = threadIdx.x, warp = t >> 5, lane = t & 31;
    __shared__ float se[DM];
    int l = (s * LK) / SKK;
    for (int j = t; j < DM; j += 256) se[j] = enc[((size_t)b * LK + l) * DM + j];
    __syncthreads();
    const float4* se4 = (const float4*)se;
    for (int row = warp; row < ROWS; row += 8) {
        const float4* qw4 = (const float4*)(g_qw + row * DM);
        float a = 0.f;
        #pragma unroll
        for (int k = 0; k < 4; k++) {
            int idx = lane + k * 32;
            float4 q = qw4[idx], e = se4[idx];
            a += q.x * e.x + q.y * e.y + q.z * e.z + q.w * e.w;
        }
        #pragma unroll
        for (int o = 16; o; o >>= 1) a += __shfl_down_sync(0xffffffffu, a, o);
        if (lane == 0) g_sc[(b * ROWS + row) * 48 + s] = a;
    }
}

// ---------------- M = max-mean; stable top-20 mask per (b,h) ----------------
__global__ void samp_select() {
    __shared__ float sM[ROWS];
    int b = blockIdx.x, t = threadIdx.x;
    if (t < ROWS) {
        const float* sc = g_sc + (b * ROWS + t) * 48;
        float mx = -1e30f, su = 0.f;
        for (int s = 0; s < SKK; s++) { float v = sc[s]; mx = fmaxf(mx, v); su += v; }
        sM[t] = mx - su * (1.0f / SKK);
    }
    __syncthreads();
    if (t < ROWS) {
        int h = t / LQ, q = t % LQ, base = h * LQ, rank = 0;
        float mv = sM[t];
        for (int i = 0; i < LQ; i++) {
            float o = sM[base + i];
            rank += (o > mv) || (o == mv && i < q);
        }
        g_istop[b * ROWS + t] = (rank < NTOP) ? 1 : 0;
    }
}

// ---------------- S GEMM: S = 0.125 * qW @ enc^T, with partial softmax stats -
__global__ void __launch_bounds__(256) s_gemm(const float* __restrict__ enc) {
    extern __shared__ float smd[];
    float* As = smd;            // [96][36]
    float* Bs = smd + 96 * 36;  // [128][36]
    int t = threadIdx.x, warp = t >> 5;
    int nt = blockIdx.x, mt = blockIdx.y, b = blockIdx.z;
    int m0 = mt * 96, n0 = nt * 128;
    int wm = warp >> 2, wn = warp & 3;

    wmma::fragment<wmma::accumulator, 16, 16, 8, float> acc[3][2];
    #pragma unroll
    for (int i = 0; i < 3; i++)
        #pragma unroll
        for (int j = 0; j < 2; j++) wmma::fill_fragment(acc[i][j], 0.0f);

    for (int k0 = 0; k0 < DM; k0 += 32) {
        #pragma unroll
        for (int i4 = t; i4 < 768; i4 += 256) {
            int r = i4 >> 3, c4 = (i4 & 7) * 4;
            *(float4*)(As + r * 36 + c4) = *(const float4*)(g_qw + (m0 + r) * DM + k0 + c4);
        }
        #pragma unroll
        for (int i4 = t; i4 < 1024; i4 += 256) {
            int l = i4 >> 3, c4 = (i4 & 7) * 4;
            *(float4*)(Bs + l * 36 + c4) =
                *(const float4*)(enc + ((size_t)b * LK + n0 + l) * DM + k0 + c4);
        }
        __syncthreads();
        if (mt == 0) {  // fused enc column sums (for v-mean)
            int c = t >> 3, g = t & 7;
            float v = 0.f;
            for (int l = g * 16; l < g * 16 + 16; l++) v += Bs[l * 36 + c];
            #pragma unroll
            for (int o = 4; o; o >>= 1) v += __shfl_down_sync(0xffffffffu, v, o);
            if (g == 0) atomicAdd(&g_encsum[b * DM + k0 + c], v);
        }
        #pragma unroll
        for (int kk = 0; kk < 4; kk++) {
            wmma::fragment<wmma::matrix_a, 16, 16, 8, wmma::precision::tf32, wmma::row_major> af[3];
            wmma::fragment<wmma::matrix_b, 16, 16, 8, wmma::precision::tf32, wmma::col_major> bf[2];
            #pragma unroll
            for (int i = 0; i < 3; i++) {
                wmma::load_matrix_sync(af[i], As + (wm * 48 + i * 16) * 36 + kk * 8, 36);
                #pragma unroll
                for (int e = 0; e < af[i].num_elements; e++) af[i].x[e] = wmma::__float_to_tf32(af[i].x[e]);
            }
            #pragma unroll
            for (int j = 0; j < 2; j++) {
                wmma::load_matrix_sync(bf[j], Bs + (wn * 32 + j * 16) * 36 + kk * 8, 36);
                #pragma unroll
                for (int e = 0; e < bf[j].num_elements; e++) bf[j].x[e] = wmma::__float_to_tf32(bf[j].x[e]);
            }
            #pragma unroll
            for (int i = 0; i < 3; i++)
                #pragma unroll
                for (int j = 0; j < 2; j++) wmma::mma_sync(acc[i][j], af[i], bf[j], acc[i][j]);
        }
        __syncthreads();
    }
    float* Ss = smd;  // [96][132] staging
    #pragma unroll
    for (int i = 0; i < 3; i++)
        #pragma unroll
        for (int j = 0; j < 2; j++)
            wmma::store_matrix_sync(Ss + (wm * 48 + i * 16) * 132 + wn * 32 + j * 16,
                                    acc[i][j], 132, wmma::mem_row_major);
    __syncthreads();
    const float scale = 0.125f;
    size_t base = ((size_t)b * RPAD + m0) * LK + n0;
    for (int i4 = t; i4 < 3072; i4 += 256) {
        int r = i4 >> 5, c4 = (i4 & 31) * 4;
        float4 v = *(float4*)(Ss + r * 132 + c4);
        v.x *= scale; v.y *= scale; v.z *= scale; v.w *= scale;
        *(float4*)(Ss + r * 132 + c4) = v;
        *(float4*)(g_S + base + (size_t)r * LK + c4) = v;
    }
    __syncthreads();
    if (t < 96) {
        float mx = -1e30f;
        for (int c = 0; c < 128; c++) mx = fmaxf(mx, Ss[t * 132 + c]);
        float su = 0.f;
        for (int c = 0; c < 128; c++) su += __expf(Ss[t * 132 + c] - mx);
        int rr = b * RPAD + m0 + t;
        g_pmax[rr * 32 + nt] = mx;
        g_psum[rr * 32 + nt] = su;
    }
}

// ---------------- merge softmax stats ----------------
__global__ void stat_merge() {
    int r = blockIdx.x * 256 + threadIdx.x;
    if (r >= NB * RPAD) return;
    float m = -1e30f;
    for (int i = 0; i < 32; i++) m = fmaxf(m, g_pmax[r * 32 + i]);
    float s = 0.f;
    for (int i = 0; i < 32; i++) s += g_psum[r * 32 + i] * __expf(g_pmax[r * 32 + i] - m);
    g_rmax[r] = m;
    g_rinv[r] = 1.0f / s;
}

// ---------------- u GEMM: u = P @ enc ----------------
__global__ void __launch_bounds__(256) u_gemm(const float* __restrict__ enc) {
    __shared__ __align__(16) float As[96 * 36];
    __shared__ __align__(16) float Bs[32 * 260];
    __shared__ float smx[96], sri[96];
    int t = threadIdx.x, warp = t >> 5;
    int gx = blockIdx.x, b = blockIdx.y;
    int nt = gx & 1, mt = (gx >> 1) & 1, kc = gx >> 2;
    int m0 = mt * 96, n0 = nt * 256;
    int wm = warp >> 2, wn = warp & 3;
    if (t < 96) { int rr = b * RPAD + m0 + t; smx[t] = g_rmax[rr]; sri[t] = g_rinv[rr]; }
    __syncthreads();

    wmma::fragment<wmma::accumulator, 16, 16, 8, float> acc[3][4];
    #pragma unroll
    for (int i = 0; i < 3; i++)
        #pragma unroll
        for (int j = 0; j < 4; j++) wmma::fill_fragment(acc[i][j], 0.0f);

    for (int k0 = kc * 2048; k0 < kc * 2048 + 2048; k0 += 32) {
        #pragma unroll
        for (int i4 = t; i4 < 768; i4 += 256) {
            int r = i4 >> 3, c0 = (i4 & 7) * 4;
            float4 s = *(const float4*)(g_S + ((size_t)b * RPAD + m0 + r) * LK + k0 + c0);
            float m = smx[r], ri = sri[r];
            float4 p;
            p.x = __expf(s.x - m) * ri;
            p.y = __expf(s.y - m) * ri;
            p.z = __expf(s.z - m) * ri;
            p.w = __expf(s.w - m) * ri;
            *(float4*)(As + r * 36 + c0) = p;
        }
        #pragma unroll
        for (int i4 = t; i4 < 2048; i4 += 256) {
            int l = i4 >> 6, c4 = (i4 & 63) * 4;
            *(float4*)(Bs + l * 260 + c4) =
                *(const float4*)(enc + ((size_t)b * LK + k0 + l) * DM + n0 + c4);
        }
        __syncthreads();
        #pragma unroll
        for (int kk = 0; kk < 4; kk++) {
            wmma::fragment<wmma::matrix_a, 16, 16, 8, wmma::precision::tf32, wmma::row_major> af[3];
            wmma::fragment<wmma::matrix_b, 16, 16, 8, wmma::precision::tf32, wmma::row_major> bf[4];
            #pragma unroll
            for (int i = 0; i < 3; i++) {
                wmma::load_matrix_sync(af[i], As + (wm * 48 + i * 16) * 36 + kk * 8, 36);
                #pragma unroll
                for (int e = 0; e < af[i].num_elements; e++) af[i].x[e] = wmma::__float_to_tf32(af[i].x[e]);
            }
            #pragma unroll
            for (int j = 0; j < 4; j++) {
                wmma::load_matrix_sync(bf[j], Bs + (kk * 8) * 260 + wn * 64 + j * 16, 260);
                #pragma unroll
                for (int e = 0; e < bf[j].num_elements; e++) bf[j].x[e] = wmma::__float_to_tf32(bf[j].x[e]);
            }
            #pragma unroll
            for (int i = 0; i < 3; i++)
                #pragma unroll
                for (int j = 0; j < 4; j++) wmma::mma_sync(acc[i][j], af[i], bf[j], acc[i][j]);
        }
        __syncthreads();
    }
    float* up = g_u + (size_t)kc * NB * RPAD * DM;
    #pragma unroll
    for (int i = 0; i < 3; i++)
        #pragma unroll
        for (int j = 0; j < 4; j++)
            wmma::store_matrix_sync(up + ((size_t)(b * RPAD + m0 + wm * 48 + i * 16)) * DM
                                       + n0 + wn * 64 + j * 16,
                                    acc[i][j], DM, wmma::mem_row_major);
}

// ---------------- ctx: top rows u@Wv_h + bv, else v-mean ----------------
__global__ void ctx_kernel(const float* __restrict__ Wv, const float* __restrict__ bv) {
    __shared__ float su[LQ * DM];
    __shared__ float svm[64];
    int bh = blockIdx.x, b = bh >> 3, h = bh & 7, t = threadIdx.x;
    const size_t ub = ((size_t)b * RPAD + h * LQ) * DM;
    const size_t half = (size_t)NB * RPAD * DM;
    for (int i = t; i < LQ * DM; i += 256) su[i] = g_u[ub + i] + g_u[half + ub + i];
    if (t < 64) {
        float a = bv[h * 64 + t];
        const float inv = 1.0f / 4096.f;
        for (int c = 0; c < DM; c++) a += g_encsum[b * DM + c] * inv * Wv[c * DM + h * 64 + t];
        svm[t] = a;
    }
    __syncthreads();
    for (int i = t; i < LQ * 64; i += 256) {
        int q = i >> 6, d = i & 63;
        float v;
        if (g_istop[b * ROWS + h * LQ + q]) {
            float a = bv[h * 64 + d];
            for (int c = 0; c < DM; c++) a += su[q * DM + c] * Wv[c * DM + h * 64 + d];
            v = a;
        } else v = svm[d];
        g_ctx[((size_t)b * LQ + q) * DM + h * 64 + d] = v;
    }
}

// ---------------- f1: x = LN(2*(ctx@Wo+bo)) ----------------
__global__ void f1_kernel(const float* __restrict__ Wo, const float* __restrict__ bo,
                          const float* __restrict__ g1, const float* __restrict__ be1) {
    int r = blockIdx.x, t = threadIdx.x;
    __shared__ float sc[DM];
    __shared__ float red[32];
    for (int j = t; j < DM; j += 256) sc[j] = g_ctx[(size_t)r * DM + j];
    __syncthreads();
    float z[2];
    #pragma unroll
    for (int u2 = 0; u2 < 2; u2++) {
        int n = t + u2 * 256;
        float a = bo[n];
        for (int k = 0; k < DM; k++) a += sc[k] * Wo[k * DM + n];
        z[u2] = 2.0f * a;
    }
    float s1 = blockReduce(z[0] + z[1], red);
    float s2 = blockReduce(z[0] * z[0] + z[1] * z[1], red);
    float mu = s1 * (1.0f / 512.f);
    float va = fmaxf(s2 * (1.0f / 512.f) - mu * mu, 0.f);
    float rs = rsqrtf(va + 1e-5f);
    #pragma unroll
    for (int u2 = 0; u2 < 2; u2++) {
        int n = t + u2 * 256;
        g_x[(size_t)r * DM + n] = (z[u2] - mu) * rs * g1[n] + be1[n];
    }
}

// ---------------- FFN GEMM: C = act(A @ Bw^T + bias [+ g_x residual]) --------
// A: [MPAD, KD] (rows >= 704 are zero), Bw: [NTOT, KD] row-major.
// tiles 96x128, 8 warps (2m x 4n), K-step 32. Writes rows < 704 only.
template<int KD, int NTOT, bool RELU, bool RESID>
__global__ void __launch_bounds__(256) ffn_gemm(const float* __restrict__ A,
                                                const float* __restrict__ Bw,
                                                const float* __restrict__ bias,
                                                float* __restrict__ C) {
    extern __shared__ float smd[];
    float* As = smd;            // [96][36]
    float* Bs = smd + 96 * 36;  // [128][36]
    int t = threadIdx.x, warp = t >> 5;
    int m0 = blockIdx.y * 96, n0 = blockIdx.x * 128;
    int wm = warp >> 2, wn = warp & 3;

    wmma::fragment<wmma::accumulator, 16, 16, 8, float> acc[3][2];
    #pragma unroll
    for (int i = 0; i < 3; i++)
        #pragma unroll
        for (int j = 0; j < 2; j++) wmma::fill_fragment(acc[i][j], 0.0f);

    for (int k0 = 0; k0 < KD; k0 += 32) {
        #pragma unroll
        for (int i4 = t; i4 < 768; i4 += 256) {
            int r = i4 >> 3, c4 = (i4 & 7) * 4;
            *(float4*)(As + r * 36 + c4) = *(const float4*)(A + (size_t)(m0 + r) * KD + k0 + c4);
        }
        #pragma unroll
        for (int i4 = t; i4 < 1024; i4 += 256) {
            int n = i4 >> 3, c4 = (i4 & 7) * 4;
            *(float4*)(Bs + n * 36 + c4) = *(const float4*)(Bw + (size_t)(n0 + n) * KD + k0 + c4);
        }
        __syncthreads();
        #pragma unroll
        for (int kk = 0; kk < 4; kk++) {
            wmma::fragment<wmma::matrix_a, 16, 16, 8, wmma::precision::tf32, wmma::row_major> af[3];
            wmma::fragment<wmma::matrix_b, 16, 16, 8, wmma::precision::tf32, wmma::col_major> bf[2];
            #pragma unroll
            for (int i = 0; i < 3; i++) {
                wmma::load_matrix_sync(af[i], As + (wm * 48 + i * 16) * 36 + kk * 8, 36);
                #pragma unroll
                for (int e = 0; e < af[i].num_elements; e++) af[i].x[e] = wmma::__float_to_tf32(af[i].x[e]);
            }
            #pragma unroll
            for (int j = 0; j < 2; j++) {
                wmma::load_matrix_sync(bf[j], Bs + (wn * 32 + j * 16) * 36 + kk * 8, 36);
                #pragma unroll
                for (int e = 0; e < bf[j].num_elements; e++) bf[j].x[e] = wmma::__float_to_tf32(bf[j].x[e]);
            }
            #pragma unroll
            for (int i = 0; i < 3; i++)
                #pragma unroll
                for (int j = 0; j < 2; j++) wmma::mma_sync(acc[i][j], af[i], bf[j], acc[i][j]);
        }
        __syncthreads();
    }
    float* Ss = smd;  // [96][132]
    #pragma unroll
    for (int i = 0; i < 3; i++)
        #pragma unroll
        for (int j = 0; j < 2; j++)
            wmma::store_matrix_sync(Ss + (wm * 48 + i * 16) * 132 + wn * 32 + j * 16,
                                    acc[i][j], 132, wmma::mem_row_major);
    __syncthreads();
    for (int i4 = t; i4 < 3072; i4 += 256) {
        int r = i4 >> 5, c4 = (i4 & 31) * 4;
        int row = m0 + r, n = n0 + c4;
        if (row >= MROWS) continue;
        float4 v = *(float4*)(Ss + r * 132 + c4);
        v.x += bias[n + 0]; v.y += bias[n + 1]; v.z += bias[n + 2]; v.w += bias[n + 3];
        if (RELU) {
            v.x = fmaxf(v.x, 0.f); v.y = fmaxf(v.y, 0.f);
            v.z = fmaxf(v.z, 0.f); v.w = fmaxf(v.w, 0.f);
        }
        if (RESID) {
            const float* xr = g_x + (size_t)row * DM + n;
            v.x += xr[0]; v.y += xr[1]; v.z += xr[2]; v.w += xr[3];
        }
        *(float4*)(C + (size_t)row * NTOT + n) = v;
    }
}

// ---------------- f3b: y = LN(z); forecast = y@Wout + bout ----------------
__global__ void f3b_kernel(const float* __restrict__ g2, const float* __restrict__ be2,
                           const float* __restrict__ Wout, const float* __restrict__ bout,
                           float* __restrict__ out) {
    int r = blockIdx.x, t = threadIdx.x;
    __shared__ float red[32];
    float z0 = g_z[(size_t)r * DM + t];
    float z1 = g_z[(size_t)r * DM + t + 256];
    float s1 = blockReduce(z0 + z1, red);
    float s2 = blockReduce(z0 * z0 + z1 * z1, red);
    float mu = s1 * (1.0f / 512.f);
    float va = fmaxf(s2 * (1.0f / 512.f) - mu * mu, 0.f);
    float rs = rsqrtf(va + 1e-5f);
    float y0 = (z0 - mu) * rs * g2[t] + be2[t];
    float y1 = (z1 - mu) * rs * g2[t + 256] + be2[t + 256];
    out[NB * LQ + (size_t)r * DM + t] = y0;
    out[NB * LQ + (size_t)r * DM + t + 256] = y1;
    float f = blockReduce(y0 * Wout[t] + y1 * Wout[t + 256], red);
    if (t == 0) out[r] = f + bout[0];
}

// ---------------- launch ----------------
extern "C" void kernel_launch(void* const* d_in, const int* in_sizes, int n_in,
                              void* d_out, int out_size) {
    const float* enc  = (const float*)d_in[0];
    const float* Wq   = (const float*)d_in[1];
    const float* bq   = (const float*)d_in[2];
    const float* Wk   = (const float*)d_in[3];
    const float* Wv   = (const float*)d_in[5];
    const float* bv   = (const float*)d_in[6];
    const float* Wo   = (const float*)d_in[7];
    const float* bo   = (const float*)d_in[8];
    const float* w1   = (const float*)d_in[9];
    const float* b1   = (const float*)d_in[10];
    const float* w2   = (const float*)d_in[11];
    const float* b2   = (const float*)d_in[12];
    const float* g1   = (const float*)d_in[13];
    const float* be1  = (const float*)d_in[14];
    const float* g2   = (const float*)d_in[15];
    const float* be2  = (const float*)d_in[16];
    const float* Wout = (const float*)d_in[17];
    const float* bout = (const float*)d_in[18];
    float* out = (float*)d_out;

    float* gx_ptr;  float* gff_ptr; float* gz_ptr;
    cudaGetSymbolAddress((void**)&gx_ptr, g_x);
    cudaGetSymbolAddress((void**)&gff_ptr, g_ff);
    cudaGetSymbolAddress((void**)&gz_ptr, g_z);

    cudaFuncSetAttribute(s_gemm, cudaFuncAttributeMaxDynamicSharedMemorySize, 53248);
    cudaFuncSetAttribute(ffn_gemm<512, 2048, true, false>,
                         cudaFuncAttributeMaxDynamicSharedMemorySize, 53248);
    cudaFuncSetAttribute(ffn_gemm<2048, 512, false, true>,
                         cudaFuncAttributeMaxDynamicSharedMemorySize, 53248);

    zero_kernel<<<64, 256>>>();
    q_kernel<<<22, 256>>>(Wq, bq);
    qw_kernel<<<176, 256>>>(Wk);
    samp_score<<<NB * SKK, 256>>>(enc);
    samp_select<<<NB, 256>>>();
    dim3 gc(32, 2, NB);
    s_gemm<<<gc, 256, 50688>>>(enc);
    stat_merge<<<24, 256>>>();
    dim3 ge(8, NB);
    u_gemm<<<ge, 256>>>(enc);
    ctx_kernel<<<256, 256>>>(Wv, bv);
    f1_kernel<<<NB * LQ, 256>>>(Wo, bo, g1, be1);
    dim3 gf1(16, 8);
    ffn_gemm<512, 2048, true, false><<<gf1, 256, 50688>>>(gx_ptr, w1, b1, gff_ptr);
    dim3 gf2(4, 8);
    ffn_gemm<2048, 512, false, true><<<gf2, 256, 50688>>>(gff_ptr, w2, b2, gz_ptr);
    f3b_kernel<<<NB * LQ, 256>>>(g2, be2, Wout, bout, out);
}

// round 5
// speedup vs baseline: 1.9265x; 1.0403x over previous
#include <cuda_runtime.h>
#include <mma.h>
#include <math.h>
#include <cstdint>

using namespace nvcuda;

#define NB   32
#define LK   4096
#define DM   512
#define NH   8
#define DH   64
#define DFF  2048
#define LQ   22
#define SKK  45
#define NTOP 20
#define ROWS 176
#define RPAD 192
#define MROWS (NB * LQ)      // 704
#define MPAD  768

// ---------------- scratch (zero-initialized device globals) ----------------
__device__ float g_q[LQ * DM];
__device__ float g_qw[RPAD * DM];                 // rows >=176 stay zero
__device__ float g_sc[NB * ROWS * 48];
__device__ unsigned char g_istop[NB * ROWS];
__device__ float g_S[(size_t)NB * RPAD * LK];     // P = exp(scaled logits)
__device__ float g_psum[NB * RPAD * 32];
__device__ float g_rinv[NB * RPAD];
__device__ float g_encsum[NB * DM];
__device__ float g_u[2 * (size_t)NB * RPAD * DM]; // split-K halves
__device__ float g_ctx[NB * LQ * DM];
__device__ float g_x[MPAD * DM];                  // rows >=704 stay zero
__device__ float g_ff[(size_t)MPAD * DFF];
__device__ float g_z[MROWS * DM];

// ---------------- async-copy helpers ----------------
__device__ __forceinline__ void cp16(float* smem, const float* gmem) {
    uint32_t s = (uint32_t)__cvta_generic_to_shared(smem);
    asm volatile("cp.async.cg.shared.global [%0], [%1], 16;" :: "r"(s), "l"(gmem));
}
__device__ __forceinline__ void cp_commit() { asm volatile("cp.async.commit_group;"); }
template<int N> __device__ __forceinline__ void cp_wait() {
    asm volatile("cp.async.wait_group %0;" :: "n"(N));
}

__device__ __forceinline__ float blockReduce(float v, float* red) {
    __syncthreads();
    #pragma unroll
    for (int o = 16; o; o >>= 1) v += __shfl_down_sync(0xffffffffu, v, o);
    int w = threadIdx.x >> 5;
    if ((threadIdx.x & 31) == 0) red[w] = v;
    __syncthreads();
    if (threadIdx.x < 32) {
        float x = (threadIdx.x < (blockDim.x >> 5)) ? red[threadIdx.x] : 0.f;
        #pragma unroll
        for (int o = 16; o; o >>= 1) x += __shfl_down_sync(0xffffffffu, x, o);
        if (threadIdx.x == 0) red[0] = x;
    }
    __syncthreads();
    return red[0];
}

// ---------------- zero encsum ----------------
__global__ void zero_kernel() {
    int i = blockIdx.x * 256 + threadIdx.x;
    if (i < NB * DM) g_encsum[i] = 0.f;
}

// ---------------- q = pe @ Wq + bq ----------------
__global__ void q_kernel(const float* __restrict__ Wq, const float* __restrict__ bq) {
    int l = blockIdx.x, t = threadIdx.x;
    __shared__ float spe[DM];
    const float c = logf(10000.0f) / 512.0f;
    for (int j = t; j < DM; j += 256) {
        int i = j >> 1;
        float arg = (float)l * expf(-(float)(2 * i) * c);
        spe[j] = (j & 1) ? cosf(arg) : sinf(arg);
    }
    __syncthreads();
    for (int n = t; n < DM; n += 256) {
        float a = bq[n];
        for (int k = 0; k < DM; k++) a += spe[k] * Wq[k * DM + n];
        g_q[l * DM + n] = a;
    }
}

// ---------------- qW[row,c] = sum_d q[q, h64+d] * Wk[c, h64+d] ----------------
__global__ void qw_kernel(const float* __restrict__ Wk) {
    int row = blockIdx.x, h = row / LQ, q = row % LQ, t = threadIdx.x;
    __shared__ float sq[64];
    if (t < 64) sq[t] = g_q[q * DM + h * 64 + t];
    __syncthreads();
    for (int c = t; c < DM; c += 256) {
        const float* wr = Wk + (size_t)c * DM + h * 64;
        float a = 0.f;
        #pragma unroll
        for (int d = 0; d < 64; d++) a += sq[d] * wr[d];
        g_qw[row * DM + c] = a;
    }
}

// ---------------- sampled scores ----------------
__global__ void __launch_bounds__(256) samp_score(const float* __restrict__ enc) {
    int b = blockIdx.x / SKK, s = blockIdx.x % SKK;
    int t = threadIdx.x, warp = t >> 5, lane = t & 31;
    __shared__ float se[DM];
    int l = (s * LK) / SKK;
    for (int j = t; j < DM; j += 256) se[j] = enc[((size_t)b * LK + l) * DM + j];
    __syncthreads();
    const float4* se4 = (const float4*)se;
    for (int row = warp; row < ROWS; row += 8) {
        const float4* qw4 = (const float4*)(g_qw + row * DM);
        float a = 0.f;
        #pragma unroll
        for (int k = 0; k < 4; k++) {
            int idx = lane + k * 32;
            float4 q = qw4[idx], e = se4[idx];
            a += q.x * e.x + q.y * e.y + q.z * e.z + q.w * e.w;
        }
        #pragma unroll
        for (int o = 16; o; o >>= 1) a += __shfl_down_sync(0xffffffffu, a, o);
        if (lane == 0) g_sc[(b * ROWS + row) * 48 + s] = a;
    }
}

// ---------------- M = max-mean; stable top-20 mask per (b,h) ----------------
__global__ void samp_select() {
    __shared__ float sM[ROWS];
    int b = blockIdx.x, t = threadIdx.x;
    if (t < ROWS) {
        const float* sc = g_sc + (b * ROWS + t) * 48;
        float mx = -1e30f, su = 0.f;
        for (int s = 0; s < SKK; s++) { float v = sc[s]; mx = fmaxf(mx, v); su += v; }
        sM[t] = mx - su * (1.0f / SKK);
    }
    __syncthreads();
    if (t < ROWS) {
        int h = t / LQ, q = t % LQ, base = h * LQ, rank = 0;
        float mv = sM[t];
        for (int i = 0; i < LQ; i++) {
            float o = sM[base + i];
            rank += (o > mv) || (o == mv && i < q);
        }
        g_istop[b * ROWS + t] = (rank < NTOP) ? 1 : 0;
    }
}

// ---------------- S GEMM: P = exp(0.125 * qW @ enc^T), partial row sums ------
// tiles 96x128, 3-stage cp.async pipeline, K=512 in steps of 32.
#define SSTG 8064   // floats per stage: As 96*36 + Bs 128*36
__global__ void __launch_bounds__(256) s_gemm(const float* __restrict__ enc) {
    extern __shared__ float smd[];
    int t = threadIdx.x, warp = t >> 5;
    int nt = blockIdx.x, mt = blockIdx.y, b = blockIdx.z;
    int m0 = mt * 96, n0 = nt * 128;
    int wm = warp >> 2, wn = warp & 3;
    const float* Ag = g_qw + (size_t)m0 * DM;
    const float* Bg = enc + ((size_t)b * LK + n0) * DM;

    auto loadStage = [&](int st, int k0) {
        float* As = smd + st * SSTG;
        float* Bs = As + 3456;
        #pragma unroll
        for (int i4 = t; i4 < 768; i4 += 256) {
            int r = i4 >> 3, c4 = (i4 & 7) * 4;
            cp16(As + r * 36 + c4, Ag + (size_t)r * DM + k0 + c4);
        }
        #pragma unroll
        for (int i4 = t; i4 < 1024; i4 += 256) {
            int l = i4 >> 3, c4 = (i4 & 7) * 4;
            cp16(Bs + l * 36 + c4, Bg + (size_t)l * DM + k0 + c4);
        }
        cp_commit();
    };

    wmma::fragment<wmma::accumulator, 16, 16, 8, float> acc[3][2];
    #pragma unroll
    for (int i = 0; i < 3; i++)
        #pragma unroll
        for (int j = 0; j < 2; j++) wmma::fill_fragment(acc[i][j], 0.0f);

    loadStage(0, 0);
    loadStage(1, 32);
    for (int ks = 0; ks < 16; ks++) {
        if (ks < 15) cp_wait<1>(); else cp_wait<0>();
        __syncthreads();
        if (ks + 2 < 16) loadStage((ks + 2) % 3, (ks + 2) * 32);
        float* As = smd + (ks % 3) * SSTG;
        float* Bs = As + 3456;
        if (mt == 0) {  // fused enc column sums (for v-mean)
            int c = t >> 3, g = t & 7;
            float v = 0.f;
            for (int l = g * 16; l < g * 16 + 16; l++) v += Bs[l * 36 + c];
            #pragma unroll
            for (int o = 4; o; o >>= 1) v += __shfl_down_sync(0xffffffffu, v, o);
            if (g == 0) atomicAdd(&g_encsum[b * DM + ks * 32 + c], v);
        }
        #pragma unroll
        for (int kk = 0; kk < 4; kk++) {
            wmma::fragment<wmma::matrix_a, 16, 16, 8, wmma::precision::tf32, wmma::row_major> af[3];
            wmma::fragment<wmma::matrix_b, 16, 16, 8, wmma::precision::tf32, wmma::col_major> bf[2];
            #pragma unroll
            for (int i = 0; i < 3; i++) {
                wmma::load_matrix_sync(af[i], As + (wm * 48 + i * 16) * 36 + kk * 8, 36);
                #pragma unroll
                for (int e = 0; e < af[i].num_elements; e++) af[i].x[e] = wmma::__float_to_tf32(af[i].x[e]);
            }
            #pragma unroll
            for (int j = 0; j < 2; j++) {
                wmma::load_matrix_sync(bf[j], Bs + (wn * 32 + j * 16) * 36 + kk * 8, 36);
                #pragma unroll
                for (int e = 0; e < bf[j].num_elements; e++) bf[j].x[e] = wmma::__float_to_tf32(bf[j].x[e]);
            }
            #pragma unroll
            for (int i = 0; i < 3; i++)
                #pragma unroll
                for (int j = 0; j < 2; j++) wmma::mma_sync(acc[i][j], af[i], bf[j], acc[i][j]);
        }
        __syncthreads();
    }
    float* Ss = smd;  // [96][132] staging
    #pragma unroll
    for (int i = 0; i < 3; i++)
        #pragma unroll
        for (int j = 0; j < 2; j++)
            wmma::store_matrix_sync(Ss + (wm * 48 + i * 16) * 132 + wn * 32 + j * 16,
                                    acc[i][j], 132, wmma::mem_row_major);
    __syncthreads();
    size_t base = ((size_t)b * RPAD + m0) * LK + n0;
    for (int i4 = t; i4 < 3072; i4 += 256) {
        int r = i4 >> 5, c4 = (i4 & 31) * 4;
        float4 v = *(float4*)(Ss + r * 132 + c4);
        v.x = __expf(v.x * 0.125f); v.y = __expf(v.y * 0.125f);
        v.z = __expf(v.z * 0.125f); v.w = __expf(v.w * 0.125f);
        *(float4*)(Ss + r * 132 + c4) = v;
        *(float4*)(g_S + base + (size_t)r * LK + c4) = v;
    }
    __syncthreads();
    if (t < 96) {
        float su = 0.f;
        for (int c = 0; c < 128; c++) su += Ss[t * 132 + c];
        g_psum[(b * RPAD + m0 + t) * 32 + nt] = su;
    }
}

// ---------------- merge row sums ----------------
__global__ void stat_merge() {
    int r = blockIdx.x * 256 + threadIdx.x;
    if (r >= NB * RPAD) return;
    float s = 0.f;
    for (int i = 0; i < 32; i++) s += g_psum[r * 32 + i];
    g_rinv[r] = 1.0f / s;
}

// ---------------- u GEMM: u = P @ enc (unnormalized), 3-stage pipeline -------
#define USTG 11776  // floats per stage: As 96*36 + Bs 32*260
__global__ void __launch_bounds__(256) u_gemm(const float* __restrict__ enc) {
    extern __shared__ float smd[];
    int t = threadIdx.x, warp = t >> 5;
    int gx = blockIdx.x, b = blockIdx.y;
    int nt = gx & 1, mt = (gx >> 1) & 1, kc = gx >> 2;
    int m0 = mt * 96, n0 = nt * 256;
    int wm = warp >> 2, wn = warp & 3;
    int kbase = kc * 2048;
    const float* Ag = g_S + ((size_t)b * RPAD + m0) * LK + kbase;
    const float* Bg = enc + ((size_t)b * LK + kbase) * DM + n0;

    auto loadStage = [&](int st, int k0) {   // k0 relative to kbase
        float* As = smd + st * USTG;
        float* Bs = As + 3456;
        #pragma unroll
        for (int i4 = t; i4 < 768; i4 += 256) {
            int r = i4 >> 3, c4 = (i4 & 7) * 4;
            cp16(As + r * 36 + c4, Ag + (size_t)r * LK + k0 + c4);
        }
        #pragma unroll
        for (int i4 = t; i4 < 2048; i4 += 256) {
            int l = i4 >> 6, c4 = (i4 & 63) * 4;
            cp16(Bs + l * 260 + c4, Bg + (size_t)(k0 + l) * DM + c4);
        }
        cp_commit();
    };

    wmma::fragment<wmma::accumulator, 16, 16, 8, float> acc[3][4];
    #pragma unroll
    for (int i = 0; i < 3; i++)
        #pragma unroll
        for (int j = 0; j < 4; j++) wmma::fill_fragment(acc[i][j], 0.0f);

    loadStage(0, 0);
    loadStage(1, 32);
    for (int ks = 0; ks < 64; ks++) {
        if (ks < 63) cp_wait<1>(); else cp_wait<0>();
        __syncthreads();
        if (ks + 2 < 64) loadStage((ks + 2) % 3, (ks + 2) * 32);
        float* As = smd + (ks % 3) * USTG;
        float* Bs = As + 3456;
        #pragma unroll
        for (int kk = 0; kk < 4; kk++) {
            wmma::fragment<wmma::matrix_a, 16, 16, 8, wmma::precision::tf32, wmma::row_major> af[3];
            wmma::fragment<wmma::matrix_b, 16, 16, 8, wmma::precision::tf32, wmma::row_major> bf[4];
            #pragma unroll
            for (int i = 0; i < 3; i++) {
                wmma::load_matrix_sync(af[i], As + (wm * 48 + i * 16) * 36 + kk * 8, 36);
                #pragma unroll
                for (int e = 0; e < af[i].num_elements; e++) af[i].x[e] = wmma::__float_to_tf32(af[i].x[e]);
            }
            #pragma unroll
            for (int j = 0; j < 4; j++) {
                wmma::load_matrix_sync(bf[j], Bs + (kk * 8) * 260 + wn * 64 + j * 16, 260);
                #pragma unroll
                for (int e = 0; e < bf[j].num_elements; e++) bf[j].x[e] = wmma::__float_to_tf32(bf[j].x[e]);
            }
            #pragma unroll
            for (int i = 0; i < 3; i++)
                #pragma unroll
                for (int j = 0; j < 4; j++) wmma::mma_sync(acc[i][j], af[i], bf[j], acc[i][j]);
        }
        __syncthreads();
    }
    float* up = g_u + (size_t)kc * NB * RPAD * DM;
    #pragma unroll
    for (int i = 0; i < 3; i++)
        #pragma unroll
        for (int j = 0; j < 4; j++)
            wmma::store_matrix_sync(up + ((size_t)(b * RPAD + m0 + wm * 48 + i * 16)) * DM
                                       + n0 + wn * 64 + j * 16,
                                    acc[i][j], DM, wmma::mem_row_major);
}

// ---------------- ctx: top rows (u*rinv)@Wv_h + bv, else v-mean --------------
__global__ void ctx_kernel(const float* __restrict__ Wv, const float* __restrict__ bv) {
    __shared__ float su[LQ * DM];
    __shared__ float svm[64];
    int bh = blockIdx.x, b = bh >> 3, h = bh & 7, t = threadIdx.x;
    const size_t ub = ((size_t)b * RPAD + h * LQ) * DM;
    const size_t half = (size_t)NB * RPAD * DM;
    for (int i = t; i < LQ * DM; i += 256) {
        int q = i >> 9;
        su[i] = (g_u[ub + i] + g_u[half + ub + i]) * g_rinv[b * RPAD + h * LQ + q];
    }
    if (t < 64) {
        float a = bv[h * 64 + t];
        const float inv = 1.0f / 4096.f;
        for (int c = 0; c < DM; c++) a += g_encsum[b * DM + c] * inv * Wv[c * DM + h * 64 + t];
        svm[t] = a;
    }
    __syncthreads();
    for (int i = t; i < LQ * 64; i += 256) {
        int q = i >> 6, d = i & 63;
        float v;
        if (g_istop[b * ROWS + h * LQ + q]) {
            float a = bv[h * 64 + d];
            for (int c = 0; c < DM; c++) a += su[q * DM + c] * Wv[c * DM + h * 64 + d];
            v = a;
        } else v = svm[d];
        g_ctx[((size_t)b * LQ + q) * DM + h * 64 + d] = v;
    }
}

// ---------------- f1: x = LN(2*(ctx@Wo+bo)) ----------------
__global__ void f1_kernel(const float* __restrict__ Wo, const float* __restrict__ bo,
                          const float* __restrict__ g1, const float* __restrict__ be1) {
    int r = blockIdx.x, t = threadIdx.x;
    __shared__ float sc[DM];
    __shared__ float red[32];
    for (int j = t; j < DM; j += 256) sc[j] = g_ctx[(size_t)r * DM + j];
    __syncthreads();
    float z[2];
    #pragma unroll
    for (int u2 = 0; u2 < 2; u2++) {
        int n = t + u2 * 256;
        float a = bo[n];
        for (int k = 0; k < DM; k++) a += sc[k] * Wo[k * DM + n];
        z[u2] = 2.0f * a;
    }
    float s1 = blockReduce(z[0] + z[1], red);
    float s2 = blockReduce(z[0] * z[0] + z[1] * z[1], red);
    float mu = s1 * (1.0f / 512.f);
    float va = fmaxf(s2 * (1.0f / 512.f) - mu * mu, 0.f);
    float rs = rsqrtf(va + 1e-5f);
    #pragma unroll
    for (int u2 = 0; u2 < 2; u2++) {
        int n = t + u2 * 256;
        g_x[(size_t)r * DM + n] = (z[u2] - mu) * rs * g1[n] + be1[n];
    }
}

// ---------------- FFN GEMM: C = act(A @ Bw^T + bias [+ g_x residual]) --------
template<int KD, int NTOT, bool RELU, bool RESID>
__global__ void __launch_bounds__(256) ffn_gemm(const float* __restrict__ A,
                                                const float* __restrict__ Bw,
                                                const float* __restrict__ bias,
                                                float* __restrict__ C) {
    extern __shared__ float smd[];
    int t = threadIdx.x, warp = t >> 5;
    int m0 = blockIdx.y * 96, n0 = blockIdx.x * 128;
    int wm = warp >> 2, wn = warp & 3;
    const float* Ag = A + (size_t)m0 * KD;
    const float* Bg = Bw + (size_t)n0 * KD;
    const int NK = KD / 32;

    auto loadStage = [&](int st, int k0) {
        float* As = smd + st * SSTG;
        float* Bs = As + 3456;
        #pragma unroll
        for (int i4 = t; i4 < 768; i4 += 256) {
            int r = i4 >> 3, c4 = (i4 & 7) * 4;
            cp16(As + r * 36 + c4, Ag + (size_t)r * KD + k0 + c4);
        }
        #pragma unroll
        for (int i4 = t; i4 < 1024; i4 += 256) {
            int n = i4 >> 3, c4 = (i4 & 7) * 4;
            cp16(Bs + n * 36 + c4, Bg + (size_t)n * KD + k0 + c4);
        }
        cp_commit();
    };

    wmma::fragment<wmma::accumulator, 16, 16, 8, float> acc[3][2];
    #pragma unroll
    for (int i = 0; i < 3; i++)
        #pragma unroll
        for (int j = 0; j < 2; j++) wmma::fill_fragment(acc[i][j], 0.0f);

    loadStage(0, 0);
    loadStage(1, 32);
    for (int ks = 0; ks < NK; ks++) {
        if (ks < NK - 1) cp_wait<1>(); else cp_wait<0>();
        __syncthreads();
        if (ks + 2 < NK) loadStage((ks + 2) % 3, (ks + 2) * 32);
        float* As = smd + (ks % 3) * SSTG;
        float* Bs = As + 3456;
        #pragma unroll
        for (int kk = 0; kk < 4; kk++) {
            wmma::fragment<wmma::matrix_a, 16, 16, 8, wmma::precision::tf32, wmma::row_major> af[3];
            wmma::fragment<wmma::matrix_b, 16, 16, 8, wmma::precision::tf32, wmma::col_major> bf[2];
            #pragma unroll
            for (int i = 0; i < 3; i++) {
                wmma::load_matrix_sync(af[i], As + (wm * 48 + i * 16) * 36 + kk * 8, 36);
                #pragma unroll
                for (int e = 0; e < af[i].num_elements; e++) af[i].x[e] = wmma::__float_to_tf32(af[i].x[e]);
            }
            #pragma unroll
            for (int j = 0; j < 2; j++) {
                wmma::load_matrix_sync(bf[j], Bs + (wn * 32 + j * 16) * 36 + kk * 8, 36);
                #pragma unroll
                for (int e = 0; e < bf[j].num_elements; e++) bf[j].x[e] = wmma::__float_to_tf32(bf[j].x[e]);
            }
            #pragma unroll
            for (int i = 0; i < 3; i++)
                #pragma unroll
                for (int j = 0; j < 2; j++) wmma::mma_sync(acc[i][j], af[i], bf[j], acc[i][j]);
        }
        __syncthreads();
    }
    float* Ss = smd;  // [96][132]
    #pragma unroll
    for (int i = 0; i < 3; i++)
        #pragma unroll
        for (int j = 0; j < 2; j++)
            wmma::store_matrix_sync(Ss + (wm * 48 + i * 16) * 132 + wn * 32 + j * 16,
                                    acc[i][j], 132, wmma::mem_row_major);
    __syncthreads();
    for (int i4 = t; i4 < 3072; i4 += 256) {
        int r = i4 >> 5, c4 = (i4 & 31) * 4;
        int row = m0 + r, n = n0 + c4;
        if (row >= MROWS) continue;
        float4 v = *(float4*)(Ss + r * 132 + c4);
        v.x += bias[n + 0]; v.y += bias[n + 1]; v.z += bias[n + 2]; v.w += bias[n + 3];
        if (RELU) {
            v.x = fmaxf(v.x, 0.f); v.y = fmaxf(v.y, 0.f);
            v.z = fmaxf(v.z, 0.f); v.w = fmaxf(v.w, 0.f);
        }
        if (RESID) {
            const float* xr = g_x + (size_t)row * DM + n;
            v.x += xr[0]; v.y += xr[1]; v.z += xr[2]; v.w += xr[3];
        }
        *(float4*)(C + (size_t)row * NTOT + n) = v;
    }
}

// ---------------- f3b: y = LN(z); forecast = y@Wout + bout ----------------
__global__ void f3b_kernel(const float* __restrict__ g2, const float* __restrict__ be2,
                           const float* __restrict__ Wout, const float* __restrict__ bout,
                           float* __restrict__ out) {
    int r = blockIdx.x, t = threadIdx.x;
    __shared__ float red[32];
    float z0 = g_z[(size_t)r * DM + t];
    float z1 = g_z[(size_t)r * DM + t + 256];
    float s1 = blockReduce(z0 + z1, red);
    float s2 = blockReduce(z0 * z0 + z1 * z1, red);
    float mu = s1 * (1.0f / 512.f);
    float va = fmaxf(s2 * (1.0f / 512.f) - mu * mu, 0.f);
    float rs = rsqrtf(va + 1e-5f);
    float y0 = (z0 - mu) * rs * g2[t] + be2[t];
    float y1 = (z1 - mu) * rs * g2[t + 256] + be2[t + 256];
    out[NB * LQ + (size_t)r * DM + t] = y0;
    out[NB * LQ + (size_t)r * DM + t + 256] = y1;
    float f = blockReduce(y0 * Wout[t] + y1 * Wout[t + 256], red);
    if (t == 0) out[r] = f + bout[0];
}

// ---------------- launch ----------------
extern "C" void kernel_launch(void* const* d_in, const int* in_sizes, int n_in,
                              void* d_out, int out_size) {
    const float* enc  = (const float*)d_in[0];
    const float* Wq   = (const float*)d_in[1];
    const float* bq   = (const float*)d_in[2];
    const float* Wk   = (const float*)d_in[3];
    const float* Wv   = (const float*)d_in[5];
    const float* bv   = (const float*)d_in[6];
    const float* Wo   = (const float*)d_in[7];
    const float* bo   = (const float*)d_in[8];
    const float* w1   = (const float*)d_in[9];
    const float* b1   = (const float*)d_in[10];
    const float* w2   = (const float*)d_in[11];
    const float* b2   = (const float*)d_in[12];
    const float* g1   = (const float*)d_in[13];
    const float* be1  = (const float*)d_in[14];
    const float* g2   = (const float*)d_in[15];
    const float* be2  = (const float*)d_in[16];
    const float* Wout = (const float*)d_in[17];
    const float* bout = (const float*)d_in[18];
    float* out = (float*)d_out;

    float* gx_ptr; float* gff_ptr; float* gz_ptr;
    cudaGetSymbolAddress((void**)&gx_ptr, g_x);
    cudaGetSymbolAddress((void**)&gff_ptr, g_ff);
    cudaGetSymbolAddress((void**)&gz_ptr, g_z);

    cudaFuncSetAttribute(s_gemm, cudaFuncAttributeMaxDynamicSharedMemorySize, 3 * SSTG * 4);
    cudaFuncSetAttribute(u_gemm, cudaFuncAttributeMaxDynamicSharedMemorySize, 3 * USTG * 4);
    cudaFuncSetAttribute(ffn_gemm<512, 2048, true, false>,
                         cudaFuncAttributeMaxDynamicSharedMemorySize, 3 * SSTG * 4);
    cudaFuncSetAttribute(ffn_gemm<2048, 512, false, true>,
                         cudaFuncAttributeMaxDynamicSharedMemorySize, 3 * SSTG * 4);

    zero_kernel<<<64, 256>>>();
    q_kernel<<<22, 256>>>(Wq, bq);
    qw_kernel<<<176, 256>>>(Wk);
    samp_score<<<NB * SKK, 256>>>(enc);
    samp_select<<<NB, 256>>>();
    dim3 gc(32, 2, NB);
    s_gemm<<<gc, 256, 3 * SSTG * 4>>>(enc);
    stat_merge<<<24, 256>>>();
    dim3 ge(8, NB);
    u_gemm<<<ge, 256, 3 * USTG * 4>>>(enc);
    ctx_kernel<<<256, 256>>>(Wv, bv);
    f1_kernel<<<NB * LQ, 256>>>(Wo, bo, g1, be1);
    dim3 gf1(16, 8);
    ffn_gemm<512, 2048, true, false><<<gf1, 256, 3 * SSTG * 4>>>(gx_ptr, w1, b1, gff_ptr);
    dim3 gf2(4, 8);
    ffn_gemm<2048, 512, false, true><<<gf2, 256, 3 * SSTG * 4>>>(gff_ptr, w2, b2, gz_ptr);
    f3b_kernel<<<NB * LQ, 256>>>(g2, be2, Wout, bout, out);
}

// round 6
// speedup vs baseline: 2.2293x; 1.1572x over previous
#include <cuda_runtime.h>
#include <mma.h>
#include <math.h>
#include <cstdint>

using namespace nvcuda;

#define NB   32
#define LK   4096
#define DM   512
#define NH   8
#define DH   64
#define DFF  2048
#define LQ   22
#define SKK  45
#define NTOP 20
#define ROWS 176
#define RPAD 192
#define MROWS (NB * LQ)      // 704
#define MPAD  768

// ---------------- scratch (zero-initialized device globals) ----------------
__device__ float g_q[LQ * DM];
__device__ float g_qw[RPAD * DM];                 // rows >=176 stay zero
__device__ float g_sc[NB * ROWS * 48];
__device__ unsigned char g_istop[NB * ROWS];
__device__ float g_S[(size_t)NB * RPAD * LK];     // P = exp(scaled logits)
__device__ float g_psum[NB * RPAD * 32];
__device__ float g_rinv[NB * RPAD];
__device__ float g_encsum[NB * DM];
__device__ float g_u[4 * (size_t)NB * RPAD * DM]; // 4 split-K parts
__device__ float g_ctx[MPAD * DM];                // rows >=704 stay zero
__device__ float g_ao[MROWS * DM];
__device__ float g_x[MPAD * DM];                  // rows >=704 stay zero
__device__ float g_ff[(size_t)MPAD * DFF];
__device__ float g_zp[4 * (size_t)MROWS * DM];    // ffn2 split-K partials

// ---------------- async-copy helpers ----------------
__device__ __forceinline__ void cp16(float* smem, const float* gmem) {
    uint32_t s = (uint32_t)__cvta_generic_to_shared(smem);
    asm volatile("cp.async.cg.shared.global [%0], [%1], 16;" :: "r"(s), "l"(gmem));
}
__device__ __forceinline__ void cp_commit() { asm volatile("cp.async.commit_group;"); }
template<int N> __device__ __forceinline__ void cp_wait() {
    asm volatile("cp.async.wait_group %0;" :: "n"(N));
}

__device__ __forceinline__ float blockReduce(float v, float* red) {
    __syncthreads();
    #pragma unroll
    for (int o = 16; o; o >>= 1) v += __shfl_down_sync(0xffffffffu, v, o);
    int w = threadIdx.x >> 5;
    if ((threadIdx.x & 31) == 0) red[w] = v;
    __syncthreads();
    if (threadIdx.x < 32) {
        float x = (threadIdx.x < (blockDim.x >> 5)) ? red[threadIdx.x] : 0.f;
        #pragma unroll
        for (int o = 16; o; o >>= 1) x += __shfl_down_sync(0xffffffffu, x, o);
        if (threadIdx.x == 0) red[0] = x;
    }
    __syncthreads();
    return red[0];
}

// ---------------- zero encsum ----------------
__global__ void zero_kernel() {
    int i = blockIdx.x * 256 + threadIdx.x;
    if (i < NB * DM) g_encsum[i] = 0.f;
}

// ---------------- q = pe @ Wq + bq ----------------
__global__ void q_kernel(const float* __restrict__ Wq, const float* __restrict__ bq) {
    int l = blockIdx.x, t = threadIdx.x;
    __shared__ float spe[DM];
    const float c = logf(10000.0f) / 512.0f;
    for (int j = t; j < DM; j += 256) {
        int i = j >> 1;
        float arg = (float)l * expf(-(float)(2 * i) * c);
        spe[j] = (j & 1) ? cosf(arg) : sinf(arg);
    }
    __syncthreads();
    for (int n = t; n < DM; n += 256) {
        float a = bq[n];
        for (int k = 0; k < DM; k++) a += spe[k] * Wq[k * DM + n];
        g_q[l * DM + n] = a;
    }
}

// ---------------- qW[row,c] = sum_d q[q, h64+d] * Wk[c, h64+d] ----------------
__global__ void qw_kernel(const float* __restrict__ Wk) {
    int row = blockIdx.x, h = row / LQ, q = row % LQ, t = threadIdx.x;
    __shared__ float sq[64];
    if (t < 64) sq[t] = g_q[q * DM + h * 64 + t];
    __syncthreads();
    for (int c = t; c < DM; c += 256) {
        const float* wr = Wk + (size_t)c * DM + h * 64;
        float a = 0.f;
        #pragma unroll
        for (int d = 0; d < 64; d++) a += sq[d] * wr[d];
        g_qw[row * DM + c] = a;
    }
}

// ---------------- sampled scores ----------------
__global__ void __launch_bounds__(256) samp_score(const float* __restrict__ enc) {
    int b = blockIdx.x / SKK, s = blockIdx.x % SKK;
    int t = threadIdx.x, warp = t >> 5, lane = t & 31;
    __shared__ float se[DM];
    int l = (s * LK) / SKK;
    for (int j = t; j < DM; j += 256) se[j] = enc[((size_t)b * LK + l) * DM + j];
    __syncthreads();
    const float4* se4 = (const float4*)se;
    for (int row = warp; row < ROWS; row += 8) {
        const float4* qw4 = (const float4*)(g_qw + row * DM);
        float a = 0.f;
        #pragma unroll
        for (int k = 0; k < 4; k++) {
            int idx = lane + k * 32;
            float4 q = qw4[idx], e = se4[idx];
            a += q.x * e.x + q.y * e.y + q.z * e.z + q.w * e.w;
        }
        #pragma unroll
        for (int o = 16; o; o >>= 1) a += __shfl_down_sync(0xffffffffu, a, o);
        if (lane == 0) g_sc[(b * ROWS + row) * 48 + s] = a;
    }
}

// ---------------- M = max-mean; stable top-20 mask per (b,h) ----------------
__global__ void samp_select() {
    __shared__ float sM[ROWS];
    int b = blockIdx.x, t = threadIdx.x;
    if (t < ROWS) {
        const float* sc = g_sc + (b * ROWS + t) * 48;
        float mx = -1e30f, su = 0.f;
        for (int s = 0; s < SKK; s++) { float v = sc[s]; mx = fmaxf(mx, v); su += v; }
        sM[t] = mx - su * (1.0f / SKK);
    }
    __syncthreads();
    if (t < ROWS) {
        int h = t / LQ, q = t % LQ, base = h * LQ, rank = 0;
        float mv = sM[t];
        for (int i = 0; i < LQ; i++) {
            float o = sM[base + i];
            rank += (o > mv) || (o == mv && i < q);
        }
        g_istop[b * ROWS + t] = (rank < NTOP) ? 1 : 0;
    }
}

// ---------------- S GEMM: P = exp(0.125 * qW @ enc^T), partial row sums ------
#define SSTG 8064   // floats per stage: As 96*36 + Bs 128*36
__global__ void __launch_bounds__(256) s_gemm(const float* __restrict__ enc) {
    extern __shared__ float smd[];
    int t = threadIdx.x, warp = t >> 5;
    int nt = blockIdx.x, mt = blockIdx.y, b = blockIdx.z;
    int m0 = mt * 96, n0 = nt * 128;
    int wm = warp >> 2, wn = warp & 3;
    const float* Ag = g_qw + (size_t)m0 * DM;
    const float* Bg = enc + ((size_t)b * LK + n0) * DM;

    auto loadStage = [&](int st, int k0) {
        float* As = smd + st * SSTG;
        float* Bs = As + 3456;
        #pragma unroll
        for (int i4 = t; i4 < 768; i4 += 256) {
            int r = i4 >> 3, c4 = (i4 & 7) * 4;
            cp16(As + r * 36 + c4, Ag + (size_t)r * DM + k0 + c4);
        }
        #pragma unroll
        for (int i4 = t; i4 < 1024; i4 += 256) {
            int l = i4 >> 3, c4 = (i4 & 7) * 4;
            cp16(Bs + l * 36 + c4, Bg + (size_t)l * DM + k0 + c4);
        }
        cp_commit();
    };

    wmma::fragment<wmma::accumulator, 16, 16, 8, float> acc[3][2];
    #pragma unroll
    for (int i = 0; i < 3; i++)
        #pragma unroll
        for (int j = 0; j < 2; j++) wmma::fill_fragment(acc[i][j], 0.0f);

    loadStage(0, 0);
    loadStage(1, 32);
    for (int ks = 0; ks < 16; ks++) {
        if (ks < 15) cp_wait<1>(); else cp_wait<0>();
        __syncthreads();
        if (ks + 2 < 16) loadStage((ks + 2) % 3, (ks + 2) * 32);
        float* As = smd + (ks % 3) * SSTG;
        float* Bs = As + 3456;
        if (mt == 0) {  // fused enc column sums (for v-mean)
            int c = t >> 3, g = t & 7;
            float v = 0.f;
            for (int l = g * 16; l < g * 16 + 16; l++) v += Bs[l * 36 + c];
            #pragma unroll
            for (int o = 4; o; o >>= 1) v += __shfl_down_sync(0xffffffffu, v, o);
            if (g == 0) atomicAdd(&g_encsum[b * DM + ks * 32 + c], v);
        }
        #pragma unroll
        for (int kk = 0; kk < 4; kk++) {
            wmma::fragment<wmma::matrix_a, 16, 16, 8, wmma::precision::tf32, wmma::row_major> af[3];
            wmma::fragment<wmma::matrix_b, 16, 16, 8, wmma::precision::tf32, wmma::col_major> bf[2];
            #pragma unroll
            for (int i = 0; i < 3; i++) {
                wmma::load_matrix_sync(af[i], As + (wm * 48 + i * 16) * 36 + kk * 8, 36);
                #pragma unroll
                for (int e = 0; e < af[i].num_elements; e++) af[i].x[e] = wmma::__float_to_tf32(af[i].x[e]);
            }
            #pragma unroll
            for (int j = 0; j < 2; j++) {
                wmma::load_matrix_sync(bf[j], Bs + (wn * 32 + j * 16) * 36 + kk * 8, 36);
                #pragma unroll
                for (int e = 0; e < bf[j].num_elements; e++) bf[j].x[e] = wmma::__float_to_tf32(bf[j].x[e]);
            }
            #pragma unroll
            for (int i = 0; i < 3; i++)
                #pragma unroll
                for (int j = 0; j < 2; j++) wmma::mma_sync(acc[i][j], af[i], bf[j], acc[i][j]);
        }
        __syncthreads();
    }
    float* Ss = smd;  // [96][132] staging
    #pragma unroll
    for (int i = 0; i < 3; i++)
        #pragma unroll
        for (int j = 0; j < 2; j++)
            wmma::store_matrix_sync(Ss + (wm * 48 + i * 16) * 132 + wn * 32 + j * 16,
                                    acc[i][j], 132, wmma::mem_row_major);
    __syncthreads();
    size_t base = ((size_t)b * RPAD + m0) * LK + n0;
    for (int i4 = t; i4 < 3072; i4 += 256) {
        int r = i4 >> 5, c4 = (i4 & 31) * 4;
        float4 v = *(float4*)(Ss + r * 132 + c4);
        v.x = __expf(v.x * 0.125f); v.y = __expf(v.y * 0.125f);
        v.z = __expf(v.z * 0.125f); v.w = __expf(v.w * 0.125f);
        *(float4*)(Ss + r * 132 + c4) = v;
        *(float4*)(g_S + base + (size_t)r * LK + c4) = v;
    }
    __syncthreads();
    if (t < 96) {
        float su = 0.f;
        for (int c = 0; c < 128; c++) su += Ss[t * 132 + c];
        g_psum[(b * RPAD + m0 + t) * 32 + nt] = su;
    }
}

// ---------------- merge row sums ----------------
__global__ void stat_merge() {
    int r = blockIdx.x * 256 + threadIdx.x;
    if (r >= NB * RPAD) return;
    float s = 0.f;
    for (int i = 0; i < 32; i++) s += g_psum[r * 32 + i];
    g_rinv[r] = 1.0f / s;
}

// ---------------- u GEMM: u = P @ enc, tiles 96x128, kc=4 split, 2-stage -----
#define USTG2 7680  // floats per stage: As 96*36 + Bs 32*132
__global__ void __launch_bounds__(256) u_gemm(const float* __restrict__ enc) {
    extern __shared__ float smd[];
    int t = threadIdx.x, warp = t >> 5;
    int gx = blockIdx.x, b = blockIdx.y;
    int nt = gx & 3, mt = (gx >> 2) & 1, kc = gx >> 3;
    int m0 = mt * 96, n0 = nt * 128;
    int wm = warp >> 2, wn = warp & 3;
    const float* Ag = g_S + ((size_t)b * RPAD + m0) * LK + kc * 1024;
    const float* Bg = enc + ((size_t)b * LK + kc * 1024) * DM + n0;

    auto loadStage = [&](int st, int k0) {
        float* As = smd + st * USTG2;
        float* Bs = As + 3456;
        #pragma unroll
        for (int i4 = t; i4 < 768; i4 += 256) {
            int r = i4 >> 3, c4 = (i4 & 7) * 4;
            cp16(As + r * 36 + c4, Ag + (size_t)r * LK + k0 + c4);
        }
        #pragma unroll
        for (int i4 = t; i4 < 1024; i4 += 256) {
            int l = i4 >> 5, c4 = (i4 & 31) * 4;
            cp16(Bs + l * 132 + c4, Bg + (size_t)(k0 + l) * DM + c4);
        }
        cp_commit();
    };

    wmma::fragment<wmma::accumulator, 16, 16, 8, float> acc[3][2];
    #pragma unroll
    for (int i = 0; i < 3; i++)
        #pragma unroll
        for (int j = 0; j < 2; j++) wmma::fill_fragment(acc[i][j], 0.0f);

    loadStage(0, 0);
    for (int ks = 0; ks < 32; ks++) {
        if (ks + 1 < 32) { loadStage((ks + 1) & 1, (ks + 1) * 32); cp_wait<1>(); }
        else cp_wait<0>();
        __syncthreads();
        float* As = smd + (ks & 1) * USTG2;
        float* Bs = As + 3456;
        #pragma unroll
        for (int kk = 0; kk < 4; kk++) {
            wmma::fragment<wmma::matrix_a, 16, 16, 8, wmma::precision::tf32, wmma::row_major> af[3];
            wmma::fragment<wmma::matrix_b, 16, 16, 8, wmma::precision::tf32, wmma::row_major> bf[2];
            #pragma unroll
            for (int i = 0; i < 3; i++) {
                wmma::load_matrix_sync(af[i], As + (wm * 48 + i * 16) * 36 + kk * 8, 36);
                #pragma unroll
                for (int e = 0; e < af[i].num_elements; e++) af[i].x[e] = wmma::__float_to_tf32(af[i].x[e]);
            }
            #pragma unroll
            for (int j = 0; j < 2; j++) {
                wmma::load_matrix_sync(bf[j], Bs + (kk * 8) * 132 + wn * 32 + j * 16, 132);
                #pragma unroll
                for (int e = 0; e < bf[j].num_elements; e++) bf[j].x[e] = wmma::__float_to_tf32(bf[j].x[e]);
            }
            #pragma unroll
            for (int i = 0; i < 3; i++)
                #pragma unroll
                for (int j = 0; j < 2; j++) wmma::mma_sync(acc[i][j], af[i], bf[j], acc[i][j]);
        }
        __syncthreads();
    }
    float* up = g_u + (size_t)kc * NB * RPAD * DM;
    #pragma unroll
    for (int i = 0; i < 3; i++)
        #pragma unroll
        for (int j = 0; j < 2; j++)
            wmma::store_matrix_sync(up + ((size_t)(b * RPAD + m0 + wm * 48 + i * 16)) * DM
                                       + n0 + wn * 32 + j * 16,
                                    acc[i][j], DM, wmma::mem_row_major);
}

// ---------------- ctx: top rows (u*rinv)@Wv_h + bv, else v-mean --------------
__global__ void ctx_kernel(const float* __restrict__ Wv, const float* __restrict__ bv) {
    __shared__ float su[LQ * DM];
    __shared__ float svm[64];
    int bh = blockIdx.x, b = bh >> 3, h = bh & 7, t = threadIdx.x;
    const size_t ub = ((size_t)b * RPAD + h * LQ) * DM;
    const size_t part = (size_t)NB * RPAD * DM;
    for (int i = t; i < LQ * DM; i += 256) {
        int q = i >> 9;
        su[i] = (g_u[ub + i] + g_u[part + ub + i] + g_u[2 * part + ub + i] + g_u[3 * part + ub + i])
                * g_rinv[b * RPAD + h * LQ + q];
    }
    if (t < 64) {
        float a = bv[h * 64 + t];
        const float inv = 1.0f / 4096.f;
        for (int c = 0; c < DM; c++) a += g_encsum[b * DM + c] * inv * Wv[c * DM + h * 64 + t];
        svm[t] = a;
    }
    __syncthreads();
    for (int i = t; i < LQ * 64; i += 256) {
        int q = i >> 6, d = i & 63;
        float v;
        if (g_istop[b * ROWS + h * LQ + q]) {
            float a = bv[h * 64 + d];
            for (int c = 0; c < DM; c++) a += su[q * DM + c] * Wv[c * DM + h * 64 + d];
            v = a;
        } else v = svm[d];
        g_ctx[((size_t)b * LQ + q) * DM + h * 64 + d] = v;
    }
}

// ---------------- o GEMM: g_ao = 2*(ctx @ Wo + bo), 96x128 tiles, 2-stage ----
__global__ void __launch_bounds__(256) o_gemm(const float* __restrict__ Wo,
                                              const float* __restrict__ bo) {
    extern __shared__ float smd[];
    int t = threadIdx.x, warp = t >> 5;
    int m0 = blockIdx.y * 96, n0 = blockIdx.x * 128;
    int wm = warp >> 2, wn = warp & 3;
    const float* Ag = g_ctx + (size_t)m0 * DM;
    const float* Bg = Wo + n0;

    auto loadStage = [&](int st, int k0) {
        float* As = smd + st * USTG2;
        float* Bs = As + 3456;
        #pragma unroll
        for (int i4 = t; i4 < 768; i4 += 256) {
            int r = i4 >> 3, c4 = (i4 & 7) * 4;
            cp16(As + r * 36 + c4, Ag + (size_t)r * DM + k0 + c4);
        }
        #pragma unroll
        for (int i4 = t; i4 < 1024; i4 += 256) {
            int l = i4 >> 5, c4 = (i4 & 31) * 4;
            cp16(Bs + l * 132 + c4, Bg + (size_t)(k0 + l) * DM + c4);
        }
        cp_commit();
    };

    wmma::fragment<wmma::accumulator, 16, 16, 8, float> acc[3][2];
    #pragma unroll
    for (int i = 0; i < 3; i++)
        #pragma unroll
        for (int j = 0; j < 2; j++) wmma::fill_fragment(acc[i][j], 0.0f);

    loadStage(0, 0);
    for (int ks = 0; ks < 16; ks++) {
        if (ks + 1 < 16) { loadStage((ks + 1) & 1, (ks + 1) * 32); cp_wait<1>(); }
        else cp_wait<0>();
        __syncthreads();
        float* As = smd + (ks & 1) * USTG2;
        float* Bs = As + 3456;
        #pragma unroll
        for (int kk = 0; kk < 4; kk++) {
            wmma::fragment<wmma::matrix_a, 16, 16, 8, wmma::precision::tf32, wmma::row_major> af[3];
            wmma::fragment<wmma::matrix_b, 16, 16, 8, wmma::precision::tf32, wmma::row_major> bf[2];
            #pragma unroll
            for (int i = 0; i < 3; i++) {
                wmma::load_matrix_sync(af[i], As + (wm * 48 + i * 16) * 36 + kk * 8, 36);
                #pragma unroll
                for (int e = 0; e < af[i].num_elements; e++) af[i].x[e] = wmma::__float_to_tf32(af[i].x[e]);
            }
            #pragma unroll
            for (int j = 0; j < 2; j++) {
                wmma::load_matrix_sync(bf[j], Bs + (kk * 8) * 132 + wn * 32 + j * 16, 132);
                #pragma unroll
                for (int e = 0; e < bf[j].num_elements; e++) bf[j].x[e] = wmma::__float_to_tf32(bf[j].x[e]);
            }
            #pragma unroll
            for (int i = 0; i < 3; i++)
                #pragma unroll
                for (int j = 0; j < 2; j++) wmma::mma_sync(acc[i][j], af[i], bf[j], acc[i][j]);
        }
        __syncthreads();
    }
    float* Ss = smd;
    #pragma unroll
    for (int i = 0; i < 3; i++)
        #pragma unroll
        for (int j = 0; j < 2; j++)
            wmma::store_matrix_sync(Ss + (wm * 48 + i * 16) * 132 + wn * 32 + j * 16,
                                    acc[i][j], 132, wmma::mem_row_major);
    __syncthreads();
    for (int i4 = t; i4 < 3072; i4 += 256) {
        int r = i4 >> 5, c4 = (i4 & 31) * 4;
        int row = m0 + r, n = n0 + c4;
        if (row >= MROWS) continue;
        float4 v = *(float4*)(Ss + r * 132 + c4);
        v.x = 2.0f * (v.x + bo[n + 0]); v.y = 2.0f * (v.y + bo[n + 1]);
        v.z = 2.0f * (v.z + bo[n + 2]); v.w = 2.0f * (v.w + bo[n + 3]);
        *(float4*)(g_ao + (size_t)row * DM + n) = v;
    }
}

// ---------------- ln1: x = LN(g_ao) ----------------
__global__ void ln1_kernel(const float* __restrict__ g1, const float* __restrict__ be1) {
    int r = blockIdx.x, t = threadIdx.x;
    __shared__ float red[32];
    float z0 = g_ao[(size_t)r * DM + t];
    float z1 = g_ao[(size_t)r * DM + t + 256];
    float s1 = blockReduce(z0 + z1, red);
    float s2 = blockReduce(z0 * z0 + z1 * z1, red);
    float mu = s1 * (1.0f / 512.f);
    float va = fmaxf(s2 * (1.0f / 512.f) - mu * mu, 0.f);
    float rs = rsqrtf(va + 1e-5f);
    g_x[(size_t)r * DM + t] = (z0 - mu) * rs * g1[t] + be1[t];
    g_x[(size_t)r * DM + t + 256] = (z1 - mu) * rs * g1[t + 256] + be1[t + 256];
}

// ---------------- ffn1: g_ff = relu(x @ w1^T + b1), 3-stage ----------------
__global__ void __launch_bounds__(256) ffn1_gemm(const float* __restrict__ w1,
                                                 const float* __restrict__ b1) {
    extern __shared__ float smd[];
    int t = threadIdx.x, warp = t >> 5;
    int m0 = blockIdx.y * 96, n0 = blockIdx.x * 128;
    int wm = warp >> 2, wn = warp & 3;
    const float* Ag = g_x + (size_t)m0 * DM;
    const float* Bg = w1 + (size_t)n0 * DM;

    auto loadStage = [&](int st, int k0) {
        float* As = smd + st * SSTG;
        float* Bs = As + 3456;
        #pragma unroll
        for (int i4 = t; i4 < 768; i4 += 256) {
            int r = i4 >> 3, c4 = (i4 & 7) * 4;
            cp16(As + r * 36 + c4, Ag + (size_t)r * DM + k0 + c4);
        }
        #pragma unroll
        for (int i4 = t; i4 < 1024; i4 += 256) {
            int n = i4 >> 3, c4 = (i4 & 7) * 4;
            cp16(Bs + n * 36 + c4, Bg + (size_t)n * DM + k0 + c4);
        }
        cp_commit();
    };

    wmma::fragment<wmma::accumulator, 16, 16, 8, float> acc[3][2];
    #pragma unroll
    for (int i = 0; i < 3; i++)
        #pragma unroll
        for (int j = 0; j < 2; j++) wmma::fill_fragment(acc[i][j], 0.0f);

    loadStage(0, 0);
    loadStage(1, 32);
    for (int ks = 0; ks < 16; ks++) {
        if (ks < 15) cp_wait<1>(); else cp_wait<0>();
        __syncthreads();
        if (ks + 2 < 16) loadStage((ks + 2) % 3, (ks + 2) * 32);
        float* As = smd + (ks % 3) * SSTG;
        float* Bs = As + 3456;
        #pragma unroll
        for (int kk = 0; kk < 4; kk++) {
            wmma::fragment<wmma::matrix_a, 16, 16, 8, wmma::precision::tf32, wmma::row_major> af[3];
            wmma::fragment<wmma::matrix_b, 16, 16, 8, wmma::precision::tf32, wmma::col_major> bf[2];
            #pragma unroll
            for (int i = 0; i < 3; i++) {
                wmma::load_matrix_sync(af[i], As + (wm * 48 + i * 16) * 36 + kk * 8, 36);
                #pragma unroll
                for (int e = 0; e < af[i].num_elements; e++) af[i].x[e] = wmma::__float_to_tf32(af[i].x[e]);
            }
            #pragma unroll
            for (int j = 0; j < 2; j++) {
                wmma::load_matrix_sync(bf[j], Bs + (wn * 32 + j * 16) * 36 + kk * 8, 36);
                #pragma unroll
                for (int e = 0; e < bf[j].num_elements; e++) bf[j].x[e] = wmma::__float_to_tf32(bf[j].x[e]);
            }
            #pragma unroll
            for (int i = 0; i < 3; i++)
                #pragma unroll
                for (int j = 0; j < 2; j++) wmma::mma_sync(acc[i][j], af[i], bf[j], acc[i][j]);
        }
        __syncthreads();
    }
    float* Ss = smd;
    #pragma unroll
    for (int i = 0; i < 3; i++)
        #pragma unroll
        for (int j = 0; j < 2; j++)
            wmma::store_matrix_sync(Ss + (wm * 48 + i * 16) * 132 + wn * 32 + j * 16,
                                    acc[i][j], 132, wmma::mem_row_major);
    __syncthreads();
    for (int i4 = t; i4 < 3072; i4 += 256) {
        int r = i4 >> 5, c4 = (i4 & 31) * 4;
        int row = m0 + r, n = n0 + c4;
        if (row >= MROWS) continue;
        float4 v = *(float4*)(Ss + r * 132 + c4);
        v.x = fmaxf(v.x + b1[n + 0], 0.f); v.y = fmaxf(v.y + b1[n + 1], 0.f);
        v.z = fmaxf(v.z + b1[n + 2], 0.f); v.w = fmaxf(v.w + b1[n + 3], 0.f);
        *(float4*)(g_ff + (size_t)row * DFF + n) = v;
    }
}

// ---------------- ffn2 partial: g_zp[kc] = ff[:,kc] @ w2[:,kc]^T, 3-stage ----
__global__ void __launch_bounds__(256) ffn2_gemm(const float* __restrict__ w2) {
    extern __shared__ float smd[];
    int t = threadIdx.x, warp = t >> 5;
    int m0 = blockIdx.y * 96, n0 = blockIdx.x * 128, kc = blockIdx.z;
    int wm = warp >> 2, wn = warp & 3;
    const float* Ag = g_ff + (size_t)m0 * DFF + kc * 512;
    const float* Bg = w2 + (size_t)n0 * DFF + kc * 512;

    auto loadStage = [&](int st, int k0) {
        float* As = smd + st * SSTG;
        float* Bs = As + 3456;
        #pragma unroll
        for (int i4 = t; i4 < 768; i4 += 256) {
            int r = i4 >> 3, c4 = (i4 & 7) * 4;
            cp16(As + r * 36 + c4, Ag + (size_t)r * DFF + k0 + c4);
        }
        #pragma unroll
        for (int i4 = t; i4 < 1024; i4 += 256) {
            int n = i4 >> 3, c4 = (i4 & 7) * 4;
            cp16(Bs + n * 36 + c4, Bg + (size_t)n * DFF + k0 + c4);
        }
        cp_commit();
    };

    wmma::fragment<wmma::accumulator, 16, 16, 8, float> acc[3][2];
    #pragma unroll
    for (int i = 0; i < 3; i++)
        #pragma unroll
        for (int j = 0; j < 2; j++) wmma::fill_fragment(acc[i][j], 0.0f);

    loadStage(0, 0);
    loadStage(1, 32);
    for (int ks = 0; ks < 16; ks++) {
        if (ks < 15) cp_wait<1>(); else cp_wait<0>();
        __syncthreads();
        if (ks + 2 < 16) loadStage((ks + 2) % 3, (ks + 2) * 32);
        float* As = smd + (ks % 3) * SSTG;
        float* Bs = As + 3456;
        #pragma unroll
        for (int kk = 0; kk < 4; kk++) {
            wmma::fragment<wmma::matrix_a, 16, 16, 8, wmma::precision::tf32, wmma::row_major> af[3];
            wmma::fragment<wmma::matrix_b, 16, 16, 8, wmma::precision::tf32, wmma::col_major> bf[2];
            #pragma unroll
            for (int i = 0; i < 3; i++) {
                wmma::load_matrix_sync(af[i], As + (wm * 48 + i * 16) * 36 + kk * 8, 36);
                #pragma unroll
                for (int e = 0; e < af[i].num_elements; e++) af[i].x[e] = wmma::__float_to_tf32(af[i].x[e]);
            }
            #pragma unroll
            for (int j = 0; j < 2; j++) {
                wmma::load_matrix_sync(bf[j], Bs + (wn * 32 + j * 16) * 36 + kk * 8, 36);
                #pragma unroll
                for (int e = 0; e < bf[j].num_elements; e++) bf[j].x[e] = wmma::__float_to_tf32(bf[j].x[e]);
            }
            #pragma unroll
            for (int i = 0; i < 3; i++)
                #pragma unroll
                for (int j = 0; j < 2; j++) wmma::mma_sync(acc[i][j], af[i], bf[j], acc[i][j]);
        }
        __syncthreads();
    }
    float* Ss = smd;
    #pragma unroll
    for (int i = 0; i < 3; i++)
        #pragma unroll
        for (int j = 0; j < 2; j++)
            wmma::store_matrix_sync(Ss + (wm * 48 + i * 16) * 132 + wn * 32 + j * 16,
                                    acc[i][j], 132, wmma::mem_row_major);
    __syncthreads();
    float* Cp = g_zp + (size_t)kc * MROWS * DM;
    for (int i4 = t; i4 < 3072; i4 += 256) {
        int r = i4 >> 5, c4 = (i4 & 31) * 4;
        int row = m0 + r, n = n0 + c4;
        if (row >= MROWS) continue;
        *(float4*)(Cp + (size_t)row * DM + n) = *(float4*)(Ss + r * 132 + c4);
    }
}

// ---------------- f3b: z = x + b2 + sum partials; y = LN(z); forecast --------
__global__ void f3b_kernel(const float* __restrict__ b2,
                           const float* __restrict__ g2, const float* __restrict__ be2,
                           const float* __restrict__ Wout, const float* __restrict__ bout,
                           float* __restrict__ out) {
    int r = blockIdx.x, t = threadIdx.x;
    __shared__ float red[32];
    const size_t part = (size_t)MROWS * DM;
    size_t o0 = (size_t)r * DM + t, o1 = o0 + 256;
    float z0 = g_x[o0] + b2[t] + g_zp[o0] + g_zp[part + o0] + g_zp[2 * part + o0] + g_zp[3 * part + o0];
    float z1 = g_x[o1] + b2[t + 256] + g_zp[o1] + g_zp[part + o1] + g_zp[2 * part + o1] + g_zp[3 * part + o1];
    float s1 = blockReduce(z0 + z1, red);
    float s2 = blockReduce(z0 * z0 + z1 * z1, red);
    float mu = s1 * (1.0f / 512.f);
    float va = fmaxf(s2 * (1.0f / 512.f) - mu * mu, 0.f);
    float rs = rsqrtf(va + 1e-5f);
    float y0 = (z0 - mu) * rs * g2[t] + be2[t];
    float y1 = (z1 - mu) * rs * g2[t + 256] + be2[t + 256];
    out[NB * LQ + (size_t)r * DM + t] = y0;
    out[NB * LQ + (size_t)r * DM + t + 256] = y1;
    float f = blockReduce(y0 * Wout[t] + y1 * Wout[t + 256], red);
    if (t == 0) out[r] = f + bout[0];
}

// ---------------- launch ----------------
extern "C" void kernel_launch(void* const* d_in, const int* in_sizes, int n_in,
                              void* d_out, int out_size) {
    const float* enc  = (const float*)d_in[0];
    const float* Wq   = (const float*)d_in[1];
    const float* bq   = (const float*)d_in[2];
    const float* Wk   = (const float*)d_in[3];
    const float* Wv   = (const float*)d_in[5];
    const float* bv   = (const float*)d_in[6];
    const float* Wo   = (const float*)d_in[7];
    const float* bo   = (const float*)d_in[8];
    const float* w1   = (const float*)d_in[9];
    const float* b1   = (const float*)d_in[10];
    const float* w2   = (const float*)d_in[11];
    const float* b2   = (const float*)d_in[12];
    const float* g1   = (const float*)d_in[13];
    const float* be1  = (const float*)d_in[14];
    const float* g2   = (const float*)d_in[15];
    const float* be2  = (const float*)d_in[16];
    const float* Wout = (const float*)d_in[17];
    const float* bout = (const float*)d_in[18];
    float* out = (float*)d_out;

    cudaFuncSetAttribute(s_gemm,    cudaFuncAttributeMaxDynamicSharedMemorySize, 3 * SSTG * 4);
    cudaFuncSetAttribute(u_gemm,    cudaFuncAttributeMaxDynamicSharedMemorySize, 2 * USTG2 * 4);
    cudaFuncSetAttribute(o_gemm,    cudaFuncAttributeMaxDynamicSharedMemorySize, 2 * USTG2 * 4);
    cudaFuncSetAttribute(ffn1_gemm, cudaFuncAttributeMaxDynamicSharedMemorySize, 3 * SSTG * 4);
    cudaFuncSetAttribute(ffn2_gemm, cudaFuncAttributeMaxDynamicSharedMemorySize, 3 * SSTG * 4);

    zero_kernel<<<64, 256>>>();                                   // 1
    q_kernel<<<22, 256>>>(Wq, bq);                                // 2
    qw_kernel<<<176, 256>>>(Wk);                                  // 3
    dim3 gc(32, 2, NB);
    s_gemm<<<gc, 256, 3 * SSTG * 4>>>(enc);                       // 4  <- ncu slot
    samp_score<<<NB * SKK, 256>>>(enc);                           // 5
    samp_select<<<NB, 256>>>();                                   // 6
    stat_merge<<<24, 256>>>();                                    // 7
    dim3 ge(32, NB);
    u_gemm<<<ge, 256, 2 * USTG2 * 4>>>(enc);                      // 8
    ctx_kernel<<<256, 256>>>(Wv, bv);                             // 9
    dim3 go(4, 8);
    o_gemm<<<go, 256, 2 * USTG2 * 4>>>(Wo, bo);                   // 10
    ln1_kernel<<<MROWS, 256>>>(g1, be1);                          // 11
    dim3 gf1(16, 8);
    ffn1_gemm<<<gf1, 256, 3 * SSTG * 4>>>(w1, b1);                // 12
    dim3 gf2(4, 8, 4);
    ffn2_gemm<<<gf2, 256, 3 * SSTG * 4>>>(w2);                    // 13
    f3b_kernel<<<MROWS, 256>>>(b2, g2, be2, Wout, bout, out);     // 14
}

// round 7
// speedup vs baseline: 4.1865x; 1.8779x over previous
#include <cuda_runtime.h>
#include <cuda_fp16.h>
#include <mma.h>
#include <math.h>
#include <cstdint>

using namespace nvcuda;

#define NB   32
#define LK   4096
#define DM   512
#define NH   8
#define DH   64
#define DFF  2048
#define LQ   22
#define SKK  45
#define NTOP 20
#define ROWS 176
#define RPAD 192
#define MROWS (NB * LQ)      // 704
#define MPAD  768

// ---------------- scratch (zero-initialized device globals) ----------------
__device__ float g_q[LQ * DM];
__device__ float g_qw[RPAD * DM];                  // fp32 (selection path)
__device__ __half g_qwh[RPAD * DM];                // fp16 copy; pad rows stay 0
__device__ __half g_ench[(size_t)NB * LK * DM];    // fp16 enc copy
__device__ float g_sc[NB * ROWS * 48];
__device__ unsigned char g_istop[NB * ROWS];
__device__ __half g_Sh[(size_t)NB * RPAD * LK];    // P = exp(scaled logits), fp16
__device__ float g_psum[NB * RPAD * 32];
__device__ float g_rinv[NB * RPAD];
__device__ float g_encsum[NB * DM];
__device__ float g_u[4 * (size_t)NB * RPAD * DM];  // 4 split-K parts (fp32)
__device__ float g_ctx[MPAD * DM];                 // rows >=704 stay zero
__device__ float g_ao[MROWS * DM];
__device__ float g_x[MPAD * DM];                   // rows >=704 stay zero
__device__ float g_ff[(size_t)MPAD * DFF];
__device__ float g_zp[4 * (size_t)MROWS * DM];     // ffn2 split-K partials

// ---------------- async-copy helpers ----------------
__device__ __forceinline__ void cp16(void* smem, const void* gmem) {
    uint32_t s = (uint32_t)__cvta_generic_to_shared(smem);
    asm volatile("cp.async.cg.shared.global [%0], [%1], 16;" :: "r"(s), "l"(gmem));
}
__device__ __forceinline__ void cp_commit() { asm volatile("cp.async.commit_group;"); }
template<int N> __device__ __forceinline__ void cp_wait() {
    asm volatile("cp.async.wait_group %0;" :: "n"(N));
}

__device__ __forceinline__ float blockReduce(float v, float* red) {
    __syncthreads();
    #pragma unroll
    for (int o = 16; o; o >>= 1) v += __shfl_down_sync(0xffffffffu, v, o);
    int w = threadIdx.x >> 5;
    if ((threadIdx.x & 31) == 0) red[w] = v;
    __syncthreads();
    if (threadIdx.x < 32) {
        float x = (threadIdx.x < (blockDim.x >> 5)) ? red[threadIdx.x] : 0.f;
        #pragma unroll
        for (int o = 16; o; o >>= 1) x += __shfl_down_sync(0xffffffffu, x, o);
        if (threadIdx.x == 0) red[0] = x;
    }
    __syncthreads();
    return red[0];
}

// ---------------- q = pe @ Wq + bq  (+ zero encsum) ----------------
__global__ void q_kernel(const float* __restrict__ Wq, const float* __restrict__ bq) {
    int l = blockIdx.x, t = threadIdx.x;
    for (int i = blockIdx.x * 256 + t; i < NB * DM; i += 22 * 256) g_encsum[i] = 0.f;
    __shared__ float spe[DM];
    const float c = logf(10000.0f) / 512.0f;
    for (int j = t; j < DM; j += 256) {
        int i = j >> 1;
        float arg = (float)l * expf(-(float)(2 * i) * c);
        spe[j] = (j & 1) ? cosf(arg) : sinf(arg);
    }
    __syncthreads();
    for (int n = t; n < DM; n += 256) {
        float a = bq[n];
        for (int k = 0; k < DM; k++) a += spe[k] * Wq[k * DM + n];
        g_q[l * DM + n] = a;
    }
}

// ---------------- qW rows (fp32 + fp16 copy) ----------------
__global__ void qw_kernel(const float* __restrict__ Wk) {
    int row = blockIdx.x, h = row / LQ, q = row % LQ, t = threadIdx.x;
    __shared__ float sq[64];
    if (t < 64) sq[t] = g_q[q * DM + h * 64 + t];
    __syncthreads();
    for (int c = t; c < DM; c += 256) {
        const float* wr = Wk + (size_t)c * DM + h * 64;
        float a = 0.f;
        #pragma unroll
        for (int d = 0; d < 64; d++) a += sq[d] * wr[d];
        g_qw[row * DM + c] = a;
        g_qwh[row * DM + c] = __float2half_rn(a);
    }
}

// ---------------- enc -> fp16 copy + column sums ----------------
// grid (LK/64, NB), block 256. Each block: 64 rows x 512 cols.
__global__ void __launch_bounds__(256) enc_cvt(const float* __restrict__ enc) {
    __shared__ float ssum[DM];
    int b = blockIdx.y, l0 = blockIdx.x * 64, t = threadIdx.x;
    int c8 = (t & 63) * 8, rg = t >> 6;       // 4 row groups
    for (int i = t; i < DM; i += 256) ssum[i] = 0.f;
    __syncthreads();
    float acc[8];
    #pragma unroll
    for (int k = 0; k < 8; k++) acc[k] = 0.f;
    const float* src = enc + ((size_t)b * LK + l0) * DM + c8;
    __half* dst = g_ench + ((size_t)b * LK + l0) * DM + c8;
    for (int i = 0; i < 16; i++) {
        int r = rg + 4 * i;
        float4 v0 = *(const float4*)(src + (size_t)r * DM);
        float4 v1 = *(const float4*)(src + (size_t)r * DM + 4);
        acc[0] += v0.x; acc[1] += v0.y; acc[2] += v0.z; acc[3] += v0.w;
        acc[4] += v1.x; acc[5] += v1.y; acc[6] += v1.z; acc[7] += v1.w;
        __half h8[8];
        h8[0] = __float2half_rn(v0.x); h8[1] = __float2half_rn(v0.y);
        h8[2] = __float2half_rn(v0.z); h8[3] = __float2half_rn(v0.w);
        h8[4] = __float2half_rn(v1.x); h8[5] = __float2half_rn(v1.y);
        h8[6] = __float2half_rn(v1.z); h8[7] = __float2half_rn(v1.w);
        *(uint4*)(dst + (size_t)r * DM) = *(uint4*)h8;
    }
    #pragma unroll
    for (int k = 0; k < 8; k++) atomicAdd(&ssum[c8 + k], acc[k]);
    __syncthreads();
    for (int c = t; c < DM; c += 256) atomicAdd(&g_encsum[b * DM + c], ssum[c]);
}

// ---------------- sampled scores (exact fp32) ----------------
__global__ void __launch_bounds__(256) samp_score(const float* __restrict__ enc) {
    int b = blockIdx.x / SKK, s = blockIdx.x % SKK;
    int t = threadIdx.x, warp = t >> 5, lane = t & 31;
    __shared__ float se[DM];
    int l = (s * LK) / SKK;
    for (int j = t; j < DM; j += 256) se[j] = enc[((size_t)b * LK + l) * DM + j];
    __syncthreads();
    const float4* se4 = (const float4*)se;
    for (int row = warp; row < ROWS; row += 8) {
        const float4* qw4 = (const float4*)(g_qw + row * DM);
        float a = 0.f;
        #pragma unroll
        for (int k = 0; k < 4; k++) {
            int idx = lane + k * 32;
            float4 q = qw4[idx], e = se4[idx];
            a += q.x * e.x + q.y * e.y + q.z * e.z + q.w * e.w;
        }
        #pragma unroll
        for (int o = 16; o; o >>= 1) a += __shfl_down_sync(0xffffffffu, a, o);
        if (lane == 0) g_sc[(b * ROWS + row) * 48 + s] = a;
    }
}

// ---------------- M = max-mean; stable top-20 mask ----------------
__global__ void samp_select() {
    __shared__ float sM[ROWS];
    int b = blockIdx.x, t = threadIdx.x;
    if (t < ROWS) {
        const float* sc = g_sc + (b * ROWS + t) * 48;
        float mx = -1e30f, su = 0.f;
        for (int s = 0; s < SKK; s++) { float v = sc[s]; mx = fmaxf(mx, v); su += v; }
        sM[t] = mx - su * (1.0f / SKK);
    }
    __syncthreads();
    if (t < ROWS) {
        int h = t / LQ, q = t % LQ, base = h * LQ, rank = 0;
        float mv = sM[t];
        for (int i = 0; i < LQ; i++) {
            float o = sM[base + i];
            rank += (o > mv) || (o == mv && i < q);
        }
        g_istop[b * ROWS + t] = (rank < NTOP) ? 1 : 0;
    }
}

// ---------------- S GEMM (fp16): P = exp(0.125 * qW @ enc^T) ------------
// tiles 96x128, k-chunk 32, 3-stage, single barrier per iter.
#define SHSTG 8960  // halfs per stage: A 96*40 + B 128*40
__global__ void __launch_bounds__(256) s_gemm(int dummy) {
    extern __shared__ __align__(16) char smraw[];
    int t = threadIdx.x, warp = t >> 5;
    int nt = blockIdx.x, mt = blockIdx.y, b = blockIdx.z;
    int m0 = mt * 96, n0 = nt * 128;
    int wm = warp >> 2, wn = warp & 3;
    const __half* Ag = g_qwh + (size_t)m0 * DM;
    const __half* Bg = g_ench + ((size_t)b * LK + n0) * DM;

    auto loadStage = [&](int st, int k0) {
        __half* As = (__half*)smraw + st * SHSTG;
        __half* Bs = As + 3840;
        for (int i4 = t; i4 < 384; i4 += 256) {
            int r = i4 >> 2, c8 = (i4 & 3) * 8;
            cp16(As + r * 40 + c8, Ag + (size_t)r * DM + k0 + c8);
        }
        #pragma unroll
        for (int i4 = t; i4 < 512; i4 += 256) {
            int l = i4 >> 2, c8 = (i4 & 3) * 8;
            cp16(Bs + l * 40 + c8, Bg + (size_t)l * DM + k0 + c8);
        }
        cp_commit();
    };

    wmma::fragment<wmma::accumulator, 16, 16, 16, float> acc[3][2];
    #pragma unroll
    for (int i = 0; i < 3; i++)
        #pragma unroll
        for (int j = 0; j < 2; j++) wmma::fill_fragment(acc[i][j], 0.0f);

    loadStage(0, 0);
    loadStage(1, 32);
    for (int ks = 0; ks < 16; ks++) {
        if (ks < 15) cp_wait<1>(); else cp_wait<0>();
        __syncthreads();
        if (ks + 2 < 16) loadStage((ks + 2) % 3, (ks + 2) * 32);
        __half* As = (__half*)smraw + (ks % 3) * SHSTG;
        __half* Bs = As + 3840;
        #pragma unroll
        for (int kk = 0; kk < 2; kk++) {
            wmma::fragment<wmma::matrix_a, 16, 16, 16, __half, wmma::row_major> af[3];
            wmma::fragment<wmma::matrix_b, 16, 16, 16, __half, wmma::col_major> bf[2];
            #pragma unroll
            for (int i = 0; i < 3; i++)
                wmma::load_matrix_sync(af[i], As + (wm * 48 + i * 16) * 40 + kk * 16, 40);
            #pragma unroll
            for (int j = 0; j < 2; j++)
                wmma::load_matrix_sync(bf[j], Bs + (wn * 32 + j * 16) * 40 + kk * 16, 40);
            #pragma unroll
            for (int i = 0; i < 3; i++)
                #pragma unroll
                for (int j = 0; j < 2; j++) wmma::mma_sync(acc[i][j], af[i], bf[j], acc[i][j]);
        }
    }
    __syncthreads();
    float* Ss = (float*)smraw;  // [96][132]
    #pragma unroll
    for (int i = 0; i < 3; i++)
        #pragma unroll
        for (int j = 0; j < 2; j++)
            wmma::store_matrix_sync(Ss + (wm * 48 + i * 16) * 132 + wn * 32 + j * 16,
                                    acc[i][j], 132, wmma::mem_row_major);
    __syncthreads();
    size_t base = ((size_t)b * RPAD + m0) * LK + n0;
    for (int i4 = t; i4 < 3072; i4 += 256) {
        int r = i4 >> 5, c4 = (i4 & 31) * 4;
        float4 v = *(float4*)(Ss + r * 132 + c4);
        v.x = __expf(v.x * 0.125f); v.y = __expf(v.y * 0.125f);
        v.z = __expf(v.z * 0.125f); v.w = __expf(v.w * 0.125f);
        *(float4*)(Ss + r * 132 + c4) = v;
        __half h4[4];
        h4[0] = __float2half_rn(v.x); h4[1] = __float2half_rn(v.y);
        h4[2] = __float2half_rn(v.z); h4[3] = __float2half_rn(v.w);
        *(uint2*)(g_Sh + base + (size_t)r * LK + c4) = *(uint2*)h4;
    }
    __syncthreads();
    if (t < 96) {
        float su = 0.f;
        for (int c = 0; c < 128; c++) su += Ss[t * 132 + c];
        g_psum[(b * RPAD + m0 + t) * 32 + nt] = su;
    }
}

// ---------------- merge row sums ----------------
__global__ void stat_merge() {
    int r = blockIdx.x * 256 + threadIdx.x;
    if (r >= NB * RPAD) return;
    float s = 0.f;
    for (int i = 0; i < 32; i++) s += g_psum[r * 32 + i];
    g_rinv[r] = 1.0f / s;
}

// ---------------- u GEMM (fp16): u = P @ enc, 96x128, kc=4, 3-stage ----------
#define UHSTG 8192  // halfs per stage: A 96*40 + B 32*136
__global__ void __launch_bounds__(256) u_gemm(int dummy) {
    extern __shared__ __align__(16) char smraw[];
    int t = threadIdx.x, warp = t >> 5;
    int gx = blockIdx.x, b = blockIdx.y;
    int nt = gx & 3, mt = (gx >> 2) & 1, kc = gx >> 3;
    int m0 = mt * 96, n0 = nt * 128;
    int wm = warp >> 2, wn = warp & 3;
    const __half* Ag = g_Sh + ((size_t)b * RPAD + m0) * LK + kc * 1024;
    const __half* Bg = g_ench + ((size_t)b * LK + kc * 1024) * DM + n0;

    auto loadStage = [&](int st, int k0) {
        __half* As = (__half*)smraw + st * UHSTG;
        __half* Bs = As + 3840;
        for (int i4 = t; i4 < 384; i4 += 256) {
            int r = i4 >> 2, c8 = (i4 & 3) * 8;
            cp16(As + r * 40 + c8, Ag + (size_t)r * LK + k0 + c8);
        }
        #pragma unroll
        for (int i4 = t; i4 < 512; i4 += 256) {
            int l = i4 >> 4, c8 = (i4 & 15) * 8;
            cp16(Bs + l * 136 + c8, Bg + (size_t)(k0 + l) * DM + c8);
        }
        cp_commit();
    };

    wmma::fragment<wmma::accumulator, 16, 16, 16, float> acc[3][2];
    #pragma unroll
    for (int i = 0; i < 3; i++)
        #pragma unroll
        for (int j = 0; j < 2; j++) wmma::fill_fragment(acc[i][j], 0.0f);

    loadStage(0, 0);
    loadStage(1, 32);
    for (int ks = 0; ks < 32; ks++) {
        if (ks < 31) cp_wait<1>(); else cp_wait<0>();
        __syncthreads();
        if (ks + 2 < 32) loadStage((ks + 2) % 3, (ks + 2) * 32);
        __half* As = (__half*)smraw + (ks % 3) * UHSTG;
        __half* Bs = As + 3840;
        #pragma unroll
        for (int kk = 0; kk < 2; kk++) {
            wmma::fragment<wmma::matrix_a, 16, 16, 16, __half, wmma::row_major> af[3];
            wmma::fragment<wmma::matrix_b, 16, 16, 16, __half, wmma::row_major> bf[2];
            #pragma unroll
            for (int i = 0; i < 3; i++)
                wmma::load_matrix_sync(af[i], As + (wm * 48 + i * 16) * 40 + kk * 16, 40);
            #pragma unroll
            for (int j = 0; j < 2; j++)
                wmma::load_matrix_sync(bf[j], Bs + (kk * 16) * 136 + wn * 32 + j * 16, 136);
            #pragma unroll
            for (int i = 0; i < 3; i++)
                #pragma unroll
                for (int j = 0; j < 2; j++) wmma::mma_sync(acc[i][j], af[i], bf[j], acc[i][j]);
        }
    }
    float* up = g_u + (size_t)kc * NB * RPAD * DM;
    #pragma unroll
    for (int i = 0; i < 3; i++)
        #pragma unroll
        for (int j = 0; j < 2; j++)
            wmma::store_matrix_sync(up + ((size_t)(b * RPAD + m0 + wm * 48 + i * 16)) * DM
                                       + n0 + wn * 32 + j * 16,
                                    acc[i][j], DM, wmma::mem_row_major);
}

// ---------------- ctx: top rows (u*rinv)@Wv_h + bv, else v-mean --------------
__global__ void ctx_kernel(const float* __restrict__ Wv, const float* __restrict__ bv) {
    __shared__ float su[LQ * DM];
    __shared__ float svm[64];
    int bh = blockIdx.x, b = bh >> 3, h = bh & 7, t = threadIdx.x;
    const size_t ub = ((size_t)b * RPAD + h * LQ) * DM;
    const size_t part = (size_t)NB * RPAD * DM;
    for (int i = t; i < LQ * DM; i += 256) {
        int q = i >> 9;
        su[i] = (g_u[ub + i] + g_u[part + ub + i] + g_u[2 * part + ub + i] + g_u[3 * part + ub + i])
                * g_rinv[b * RPAD + h * LQ + q];
    }
    if (t < 64) {
        float a = bv[h * 64 + t];
        const float inv = 1.0f / 4096.f;
        for (int c = 0; c < DM; c++) a += g_encsum[b * DM + c] * inv * Wv[c * DM + h * 64 + t];
        svm[t] = a;
    }
    __syncthreads();
    for (int i = t; i < LQ * 64; i += 256) {
        int q = i >> 6, d = i & 63;
        float v;
        if (g_istop[b * ROWS + h * LQ + q]) {
            float a = bv[h * 64 + d];
            for (int c = 0; c < DM; c++) a += su[q * DM + c] * Wv[c * DM + h * 64 + d];
            v = a;
        } else v = svm[d];
        g_ctx[((size_t)b * LQ + q) * DM + h * 64 + d] = v;
    }
}

// ---------------- o GEMM (tf32): g_ao = 2*(ctx @ Wo + bo), 3-stage -----------
#define OSTG 7680  // floats per stage: As 96*36 + Bs 32*132
__global__ void __launch_bounds__(256) o_gemm(const float* __restrict__ Wo,
                                              const float* __restrict__ bo) {
    extern __shared__ __align__(16) char smraw[];
    float* smd = (float*)smraw;
    int t = threadIdx.x, warp = t >> 5;
    int m0 = blockIdx.y * 96, n0 = blockIdx.x * 128;
    int wm = warp >> 2, wn = warp & 3;
    const float* Ag = g_ctx + (size_t)m0 * DM;
    const float* Bg = Wo + n0;

    auto loadStage = [&](int st, int k0) {
        float* As = smd + st * OSTG;
        float* Bs = As + 3456;
        #pragma unroll
        for (int i4 = t; i4 < 768; i4 += 256) {
            int r = i4 >> 3, c4 = (i4 & 7) * 4;
            cp16(As + r * 36 + c4, Ag + (size_t)r * DM + k0 + c4);
        }
        #pragma unroll
        for (int i4 = t; i4 < 1024; i4 += 256) {
            int l = i4 >> 5, c4 = (i4 & 31) * 4;
            cp16(Bs + l * 132 + c4, Bg + (size_t)(k0 + l) * DM + c4);
        }
        cp_commit();
    };

    wmma::fragment<wmma::accumulator, 16, 16, 8, float> acc[3][2];
    #pragma unroll
    for (int i = 0; i < 3; i++)
        #pragma unroll
        for (int j = 0; j < 2; j++) wmma::fill_fragment(acc[i][j], 0.0f);

    loadStage(0, 0);
    loadStage(1, 32);
    for (int ks = 0; ks < 16; ks++) {
        if (ks < 15) cp_wait<1>(); else cp_wait<0>();
        __syncthreads();
        if (ks + 2 < 16) loadStage((ks + 2) % 3, (ks + 2) * 32);
        float* As = smd + (ks % 3) * OSTG;
        float* Bs = As + 3456;
        #pragma unroll
        for (int kk = 0; kk < 4; kk++) {
            wmma::fragment<wmma::matrix_a, 16, 16, 8, wmma::precision::tf32, wmma::row_major> af[3];
            wmma::fragment<wmma::matrix_b, 16, 16, 8, wmma::precision::tf32, wmma::row_major> bf[2];
            #pragma unroll
            for (int i = 0; i < 3; i++) {
                wmma::load_matrix_sync(af[i], As + (wm * 48 + i * 16) * 36 + kk * 8, 36);
                #pragma unroll
                for (int e = 0; e < af[i].num_elements; e++) af[i].x[e] = wmma::__float_to_tf32(af[i].x[e]);
            }
            #pragma unroll
            for (int j = 0; j < 2; j++) {
                wmma::load_matrix_sync(bf[j], Bs + (kk * 8) * 132 + wn * 32 + j * 16, 132);
                #pragma unroll
                for (int e = 0; e < bf[j].num_elements; e++) bf[j].x[e] = wmma::__float_to_tf32(bf[j].x[e]);
            }
            #pragma unroll
            for (int i = 0; i < 3; i++)
                #pragma unroll
                for (int j = 0; j < 2; j++) wmma::mma_sync(acc[i][j], af[i], bf[j], acc[i][j]);
        }
    }
    __syncthreads();
    float* Ss = smd;
    #pragma unroll
    for (int i = 0; i < 3; i++)
        #pragma unroll
        for (int j = 0; j < 2; j++)
            wmma::store_matrix_sync(Ss + (wm * 48 + i * 16) * 132 + wn * 32 + j * 16,
                                    acc[i][j], 132, wmma::mem_row_major);
    __syncthreads();
    for (int i4 = t; i4 < 3072; i4 += 256) {
        int r = i4 >> 5, c4 = (i4 & 31) * 4;
        int row = m0 + r, n = n0 + c4;
        if (row >= MROWS) continue;
        float4 v = *(float4*)(Ss + r * 132 + c4);
        v.x = 2.0f * (v.x + bo[n + 0]); v.y = 2.0f * (v.y + bo[n + 1]);
        v.z = 2.0f * (v.z + bo[n + 2]); v.w = 2.0f * (v.w + bo[n + 3]);
        *(float4*)(g_ao + (size_t)row * DM + n) = v;
    }
}

// ---------------- ln1: x = LN(g_ao) ----------------
__global__ void ln1_kernel(const float* __restrict__ g1, const float* __restrict__ be1) {
    int r = blockIdx.x, t = threadIdx.x;
    __shared__ float red[32];
    float z0 = g_ao[(size_t)r * DM + t];
    float z1 = g_ao[(size_t)r * DM + t + 256];
    float s1 = blockReduce(z0 + z1, red);
    float s2 = blockReduce(z0 * z0 + z1 * z1, red);
    float mu = s1 * (1.0f / 512.f);
    float va = fmaxf(s2 * (1.0f / 512.f) - mu * mu, 0.f);
    float rs = rsqrtf(va + 1e-5f);
    g_x[(size_t)r * DM + t] = (z0 - mu) * rs * g1[t] + be1[t];
    g_x[(size_t)r * DM + t + 256] = (z1 - mu) * rs * g1[t + 256] + be1[t + 256];
}

// ---------------- FFN GEMMs (tf32, 3-stage single-barrier) ----------------
#define SSTG 8064   // floats per stage: As 96*36 + Bs 128*36
__global__ void __launch_bounds__(256) ffn1_gemm(const float* __restrict__ w1,
                                                 const float* __restrict__ b1) {
    extern __shared__ __align__(16) char smraw[];
    float* smd = (float*)smraw;
    int t = threadIdx.x, warp = t >> 5;
    int m0 = blockIdx.y * 96, n0 = blockIdx.x * 128;
    int wm = warp >> 2, wn = warp & 3;
    const float* Ag = g_x + (size_t)m0 * DM;
    const float* Bg = w1 + (size_t)n0 * DM;

    auto loadStage = [&](int st, int k0) {
        float* As = smd + st * SSTG;
        float* Bs = As + 3456;
        #pragma unroll
        for (int i4 = t; i4 < 768; i4 += 256) {
            int r = i4 >> 3, c4 = (i4 & 7) * 4;
            cp16(As + r * 36 + c4, Ag + (size_t)r * DM + k0 + c4);
        }
        #pragma unroll
        for (int i4 = t; i4 < 1024; i4 += 256) {
            int n = i4 >> 3, c4 = (i4 & 7) * 4;
            cp16(Bs + n * 36 + c4, Bg + (size_t)n * DM + k0 + c4);
        }
        cp_commit();
    };

    wmma::fragment<wmma::accumulator, 16, 16, 8, float> acc[3][2];
    #pragma unroll
    for (int i = 0; i < 3; i++)
        #pragma unroll
        for (int j = 0; j < 2; j++) wmma::fill_fragment(acc[i][j], 0.0f);

    loadStage(0, 0);
    loadStage(1, 32);
    for (int ks = 0; ks < 16; ks++) {
        if (ks < 15) cp_wait<1>(); else cp_wait<0>();
        __syncthreads();
        if (ks + 2 < 16) loadStage((ks + 2) % 3, (ks + 2) * 32);
        float* As = smd + (ks % 3) * SSTG;
        float* Bs = As + 3456;
        #pragma unroll
        for (int kk = 0; kk < 4; kk++) {
            wmma::fragment<wmma::matrix_a, 16, 16, 8, wmma::precision::tf32, wmma::row_major> af[3];
            wmma::fragment<wmma::matrix_b, 16, 16, 8, wmma::precision::tf32, wmma::col_major> bf[2];
            #pragma unroll
            for (int i = 0; i < 3; i++) {
                wmma::load_matrix_sync(af[i], As + (wm * 48 + i * 16) * 36 + kk * 8, 36);
                #pragma unroll
                for (int e = 0; e < af[i].num_elements; e++) af[i].x[e] = wmma::__float_to_tf32(af[i].x[e]);
            }
            #pragma unroll
            for (int j = 0; j < 2; j++) {
                wmma::load_matrix_sync(bf[j], Bs + (wn * 32 + j * 16) * 36 + kk * 8, 36);
                #pragma unroll
                for (int e = 0; e < bf[j].num_elements; e++) bf[j].x[e] = wmma::__float_to_tf32(bf[j].x[e]);
            }
            #pragma unroll
            for (int i = 0; i < 3; i++)
                #pragma unroll
                for (int j = 0; j < 2; j++) wmma::mma_sync(acc[i][j], af[i], bf[j], acc[i][j]);
        }
    }
    __syncthreads();
    float* Ss = smd;
    #pragma unroll
    for (int i = 0; i < 3; i++)
        #pragma unroll
        for (int j = 0; j < 2; j++)
            wmma::store_matrix_sync(Ss + (wm * 48 + i * 16) * 132 + wn * 32 + j * 16,
                                    acc[i][j], 132, wmma::mem_row_major);
    __syncthreads();
    for (int i4 = t; i4 < 3072; i4 += 256) {
        int r = i4 >> 5, c4 = (i4 & 31) * 4;
        int row = m0 + r, n = n0 + c4;
        if (row >= MROWS) continue;
        float4 v = *(float4*)(Ss + r * 132 + c4);
        v.x = fmaxf(v.x + b1[n + 0], 0.f); v.y = fmaxf(v.y + b1[n + 1], 0.f);
        v.z = fmaxf(v.z + b1[n + 2], 0.f); v.w = fmaxf(v.w + b1[n + 3], 0.f);
        *(float4*)(g_ff + (size_t)row * DFF + n) = v;
    }
}

__global__ void __launch_bounds__(256) ffn2_gemm(const float* __restrict__ w2) {
    extern __shared__ __align__(16) char smraw[];
    float* smd = (float*)smraw;
    int t = threadIdx.x, warp = t >> 5;
    int m0 = blockIdx.y * 96, n0 = blockIdx.x * 128, kc = blockIdx.z;
    int wm = warp >> 2, wn = warp & 3;
    const float* Ag = g_ff + (size_t)m0 * DFF + kc * 512;
    const float* Bg = w2 + (size_t)n0 * DFF + kc * 512;

    auto loadStage = [&](int st, int k0) {
        float* As = smd + st * SSTG;
        float* Bs = As + 3456;
        #pragma unroll
        for (int i4 = t; i4 < 768; i4 += 256) {
            int r = i4 >> 3, c4 = (i4 & 7) * 4;
            cp16(As + r * 36 + c4, Ag + (size_t)r * DFF + k0 + c4);
        }
        #pragma unroll
        for (int i4 = t; i4 < 1024; i4 += 256) {
            int n = i4 >> 3, c4 = (i4 & 7) * 4;
            cp16(Bs + n * 36 + c4, Bg + (size_t)n * DFF + k0 + c4);
        }
        cp_commit();
    };

    wmma::fragment<wmma::accumulator, 16, 16, 8, float> acc[3][2];
    #pragma unroll
    for (int i = 0; i < 3; i++)
        #pragma unroll
        for (int j = 0; j < 2; j++) wmma::fill_fragment(acc[i][j], 0.0f);

    loadStage(0, 0);
    loadStage(1, 32);
    for (int ks = 0; ks < 16; ks++) {
        if (ks < 15) cp_wait<1>(); else cp_wait<0>();
        __syncthreads();
        if (ks + 2 < 16) loadStage((ks + 2) % 3, (ks + 2) * 32);
        float* As = smd + (ks % 3) * SSTG;
        float* Bs = As + 3456;
        #pragma unroll
        for (int kk = 0; kk < 4; kk++) {
            wmma::fragment<wmma::matrix_a, 16, 16, 8, wmma::precision::tf32, wmma::row_major> af[3];
            wmma::fragment<wmma::matrix_b, 16, 16, 8, wmma::precision::tf32, wmma::col_major> bf[2];
            #pragma unroll
            for (int i = 0; i < 3; i++) {
                wmma::load_matrix_sync(af[i], As + (wm * 48 + i * 16) * 36 + kk * 8, 36);
                #pragma unroll
                for (int e = 0; e < af[i].num_elements; e++) af[i].x[e] = wmma::__float_to_tf32(af[i].x[e]);
            }
            #pragma unroll
            for (int j = 0; j < 2; j++) {
                wmma::load_matrix_sync(bf[j], Bs + (wn * 32 + j * 16) * 36 + kk * 8, 36);
                #pragma unroll
                for (int e = 0; e < bf[j].num_elements; e++) bf[j].x[e] = wmma::__float_to_tf32(bf[j].x[e]);
            }
            #pragma unroll
            for (int i = 0; i < 3; i++)
                #pragma unroll
                for (int j = 0; j < 2; j++) wmma::mma_sync(acc[i][j], af[i], bf[j], acc[i][j]);
        }
    }
    __syncthreads();
    float* Ss = smd;
    #pragma unroll
    for (int i = 0; i < 3; i++)
        #pragma unroll
        for (int j = 0; j < 2; j++)
            wmma::store_matrix_sync(Ss + (wm * 48 + i * 16) * 132 + wn * 32 + j * 16,
                                    acc[i][j], 132, wmma::mem_row_major);
    __syncthreads();
    float* Cp = g_zp + (size_t)kc * MROWS * DM;
    for (int i4 = t; i4 < 3072; i4 += 256) {
        int r = i4 >> 5, c4 = (i4 & 31) * 4;
        int row = m0 + r, n = n0 + c4;
        if (row >= MROWS) continue;
        *(float4*)(Cp + (size_t)row * DM + n) = *(float4*)(Ss + r * 132 + c4);
    }
}

// ---------------- f3b: z = x + b2 + sum partials; y = LN(z); forecast --------
__global__ void f3b_kernel(const float* __restrict__ b2,
                           const float* __restrict__ g2, const float* __restrict__ be2,
                           const float* __restrict__ Wout, const float* __restrict__ bout,
                           float* __restrict__ out) {
    int r = blockIdx.x, t = threadIdx.x;
    __shared__ float red[32];
    const size_t part = (size_t)MROWS * DM;
    size_t o0 = (size_t)r * DM + t, o1 = o0 + 256;
    float z0 = g_x[o0] + b2[t] + g_zp[o0] + g_zp[part + o0] + g_zp[2 * part + o0] + g_zp[3 * part + o0];
    float z1 = g_x[o1] + b2[t + 256] + g_zp[o1] + g_zp[part + o1] + g_zp[2 * part + o1] + g_zp[3 * part + o1];
    float s1 = blockReduce(z0 + z1, red);
    float s2 = blockReduce(z0 * z0 + z1 * z1, red);
    float mu = s1 * (1.0f / 512.f);
    float va = fmaxf(s2 * (1.0f / 512.f) - mu * mu, 0.f);
    float rs = rsqrtf(va + 1e-5f);
    float y0 = (z0 - mu) * rs * g2[t] + be2[t];
    float y1 = (z1 - mu) * rs * g2[t + 256] + be2[t + 256];
    out[NB * LQ + (size_t)r * DM + t] = y0;
    out[NB * LQ + (size_t)r * DM + t + 256] = y1;
    float f = blockReduce(y0 * Wout[t] + y1 * Wout[t + 256], red);
    if (t == 0) out[r] = f + bout[0];
}

// ---------------- launch ----------------
extern "C" void kernel_launch(void* const* d_in, const int* in_sizes, int n_in,
                              void* d_out, int out_size) {
    const float* enc  = (const float*)d_in[0];
    const float* Wq   = (const float*)d_in[1];
    const float* bq   = (const float*)d_in[2];
    const float* Wk   = (const float*)d_in[3];
    const float* Wv   = (const float*)d_in[5];
    const float* bv   = (const float*)d_in[6];
    const float* Wo   = (const float*)d_in[7];
    const float* bo   = (const float*)d_in[8];
    const float* w1   = (const float*)d_in[9];
    const float* b1   = (const float*)d_in[10];
    const float* w2   = (const float*)d_in[11];
    const float* b2   = (const float*)d_in[12];
    const float* g1   = (const float*)d_in[13];
    const float* be1  = (const float*)d_in[14];
    const float* g2   = (const float*)d_in[15];
    const float* be2  = (const float*)d_in[16];
    const float* Wout = (const float*)d_in[17];
    const float* bout = (const float*)d_in[18];
    float* out = (float*)d_out;

    cudaFuncSetAttribute(s_gemm,    cudaFuncAttributeMaxDynamicSharedMemorySize, 3 * SHSTG * 2);
    cudaFuncSetAttribute(u_gemm,    cudaFuncAttributeMaxDynamicSharedMemorySize, 3 * UHSTG * 2);
    cudaFuncSetAttribute(o_gemm,    cudaFuncAttributeMaxDynamicSharedMemorySize, 3 * OSTG * 4);
    cudaFuncSetAttribute(ffn1_gemm, cudaFuncAttributeMaxDynamicSharedMemorySize, 3 * SSTG * 4);
    cudaFuncSetAttribute(ffn2_gemm, cudaFuncAttributeMaxDynamicSharedMemorySize, 3 * SSTG * 4);

    q_kernel<<<22, 256>>>(Wq, bq);                                // 1 (+zero encsum)
    qw_kernel<<<176, 256>>>(Wk);                                  // 2
    dim3 gcv(LK / 64, NB);
    enc_cvt<<<gcv, 256>>>(enc);                                   // 3
    dim3 gc(32, 2, NB);
    s_gemm<<<gc, 256, 3 * SHSTG * 2>>>(0);                        // 4  <- ncu slot
    samp_score<<<NB * SKK, 256>>>(enc);                           // 5
    samp_select<<<NB, 256>>>();                                   // 6
    stat_merge<<<24, 256>>>();                                    // 7
    dim3 ge(32, NB);
    u_gemm<<<ge, 256, 3 * UHSTG * 2>>>(0);                        // 8
    ctx_kernel<<<256, 256>>>(Wv, bv);                             // 9
    dim3 go(4, 8);
    o_gemm<<<go, 256, 3 * OSTG * 4>>>(Wo, bo);                    // 10
    ln1_kernel<<<MROWS, 256>>>(g1, be1);                          // 11
    dim3 gf1(16, 8);
    ffn1_gemm<<<gf1, 256, 3 * SSTG * 4>>>(w1, b1);                // 12
    dim3 gf2(4, 8, 4);
    ffn2_gemm<<<gf2, 256, 3 * SSTG * 4>>>(w2);                    // 13
    f3b_kernel<<<MROWS, 256>>>(b2, g2, be2, Wout, bout, out);     // 14
}

// round 8
// speedup vs baseline: 4.5854x; 1.0953x over previous
#include <cuda_runtime.h>
#include <cuda_fp16.h>
#include <mma.h>
#include <math.h>
#include <cstdint>

using namespace nvcuda;

#define NB   32
#define LK   4096
#define DM   512
#define NH   8
#define DH   64
#define DFF  2048
#define LQ   22
#define SKK  45
#define NTOP 20
#define ROWS 176
#define RPAD 192
#define MROWS (NB * LQ)      // 704
#define MPAD  768

// ---------------- scratch (zero-initialized device globals) ----------------
__device__ float g_q[LQ * DM];
__device__ float g_qw[RPAD * DM];                  // fp32 (selection path)
__device__ __half g_qwh[RPAD * DM];                // fp16 copy; pad rows stay 0
__device__ __half g_ench[(size_t)NB * LK * DM];    // fp16 enc copy
__device__ float g_sc[NB * ROWS * 48];
__device__ unsigned char g_istop[NB * ROWS];
__device__ __half g_Sh[(size_t)NB * RPAD * LK];    // P = exp(scaled logits), fp16
__device__ float g_psum[NB * RPAD * 32];
__device__ float g_rinv[NB * RPAD];
__device__ float g_encsum[NB * DM];
__device__ __half g_uh[4 * (size_t)NB * RPAD * DM]; // 4 split-K partials, fp16
__device__ float g_ctx[MPAD * DM];                 // rows >=704 stay zero
__device__ float g_ao[MROWS * DM];
__device__ float g_x[MPAD * DM];                   // rows >=704 stay zero
__device__ __half g_xh[MPAD * DM];                 // fp16 copy; pad rows stay 0
__device__ __half g_w1h[DFF * DM];
__device__ __half g_w2h[DM * DFF];
__device__ __half g_ffh[(size_t)MPAD * DFF];       // pad rows stay 0
__device__ float g_zp[4 * (size_t)MROWS * DM];     // ffn2 split-K partials

// ---------------- async-copy helpers ----------------
__device__ __forceinline__ void cp16(void* smem, const void* gmem) {
    uint32_t s = (uint32_t)__cvta_generic_to_shared(smem);
    asm volatile("cp.async.cg.shared.global [%0], [%1], 16;" :: "r"(s), "l"(gmem));
}
__device__ __forceinline__ void cp_commit() { asm volatile("cp.async.commit_group;"); }
template<int N> __device__ __forceinline__ void cp_wait() {
    asm volatile("cp.async.wait_group %0;" :: "n"(N));
}

__device__ __forceinline__ float blockReduce(float v, float* red) {
    __syncthreads();
    #pragma unroll
    for (int o = 16; o; o >>= 1) v += __shfl_down_sync(0xffffffffu, v, o);
    int w = threadIdx.x >> 5;
    if ((threadIdx.x & 31) == 0) red[w] = v;
    __syncthreads();
    if (threadIdx.x < 32) {
        float x = (threadIdx.x < (blockDim.x >> 5)) ? red[threadIdx.x] : 0.f;
        #pragma unroll
        for (int o = 16; o; o >>= 1) x += __shfl_down_sync(0xffffffffu, x, o);
        if (threadIdx.x == 0) red[0] = x;
    }
    __syncthreads();
    return red[0];
}

// ---------------- q = pe @ Wq + bq  (+ zero encsum) ----------------
__global__ void q_kernel(const float* __restrict__ Wq, const float* __restrict__ bq) {
    int l = blockIdx.x, t = threadIdx.x;
    for (int i = blockIdx.x * 256 + t; i < NB * DM; i += 22 * 256) g_encsum[i] = 0.f;
    __shared__ float spe[DM];
    const float c = logf(10000.0f) / 512.0f;
    for (int j = t; j < DM; j += 256) {
        int i = j >> 1;
        float arg = (float)l * expf(-(float)(2 * i) * c);
        spe[j] = (j & 1) ? cosf(arg) : sinf(arg);
    }
    __syncthreads();
    for (int n = t; n < DM; n += 256) {
        float a = bq[n];
        for (int k = 0; k < DM; k++) a += spe[k] * Wq[k * DM + n];
        g_q[l * DM + n] = a;
    }
}

// ---------------- qW rows (fp32 + fp16 copy) ----------------
__global__ void qw_kernel(const float* __restrict__ Wk) {
    int row = blockIdx.x, h = row / LQ, q = row % LQ, t = threadIdx.x;
    __shared__ float sq[64];
    if (t < 64) sq[t] = g_q[q * DM + h * 64 + t];
    __syncthreads();
    for (int c = t; c < DM; c += 256) {
        const float* wr = Wk + (size_t)c * DM + h * 64;
        float a = 0.f;
        #pragma unroll
        for (int d = 0; d < 64; d++) a += sq[d] * wr[d];
        g_qw[row * DM + c] = a;
        g_qwh[row * DM + c] = __float2half_rn(a);
    }
}

// ---------------- weights -> fp16 ----------------
__global__ void __launch_bounds__(256) wcvt(const float* __restrict__ w1,
                                            const float* __restrict__ w2) {
    const int TOT = DFF * DM;   // per matrix
    int i = (blockIdx.x * 256 + threadIdx.x) * 4;
    if (i < TOT) {
        float4 v = *(const float4*)(w1 + i);
        __half h4[4] = {__float2half_rn(v.x), __float2half_rn(v.y),
                        __float2half_rn(v.z), __float2half_rn(v.w)};
        *(uint2*)(g_w1h + i) = *(uint2*)h4;
        float4 u = *(const float4*)(w2 + i);
        __half g4[4] = {__float2half_rn(u.x), __float2half_rn(u.y),
                        __float2half_rn(u.z), __float2half_rn(u.w)};
        *(uint2*)(g_w2h + i) = *(uint2*)g4;
    }
}

// ---------------- enc -> fp16 copy + column sums ----------------
__global__ void __launch_bounds__(256) enc_cvt(const float* __restrict__ enc) {
    __shared__ float ssum[DM];
    int b = blockIdx.y, l0 = blockIdx.x * 64, t = threadIdx.x;
    int c8 = (t & 63) * 8, rg = t >> 6;
    for (int i = t; i < DM; i += 256) ssum[i] = 0.f;
    __syncthreads();
    float acc[8];
    #pragma unroll
    for (int k = 0; k < 8; k++) acc[k] = 0.f;
    const float* src = enc + ((size_t)b * LK + l0) * DM + c8;
    __half* dst = g_ench + ((size_t)b * LK + l0) * DM + c8;
    for (int i = 0; i < 16; i++) {
        int r = rg + 4 * i;
        float4 v0 = *(const float4*)(src + (size_t)r * DM);
        float4 v1 = *(const float4*)(src + (size_t)r * DM + 4);
        acc[0] += v0.x; acc[1] += v0.y; acc[2] += v0.z; acc[3] += v0.w;
        acc[4] += v1.x; acc[5] += v1.y; acc[6] += v1.z; acc[7] += v1.w;
        __half h8[8];
        h8[0] = __float2half_rn(v0.x); h8[1] = __float2half_rn(v0.y);
        h8[2] = __float2half_rn(v0.z); h8[3] = __float2half_rn(v0.w);
        h8[4] = __float2half_rn(v1.x); h8[5] = __float2half_rn(v1.y);
        h8[6] = __float2half_rn(v1.z); h8[7] = __float2half_rn(v1.w);
        *(uint4*)(dst + (size_t)r * DM) = *(uint4*)h8;
    }
    #pragma unroll
    for (int k = 0; k < 8; k++) atomicAdd(&ssum[c8 + k], acc[k]);
    __syncthreads();
    for (int c = t; c < DM; c += 256) atomicAdd(&g_encsum[b * DM + c], ssum[c]);
}

// ---------------- sampled scores (exact fp32) ----------------
__global__ void __launch_bounds__(256) samp_score(const float* __restrict__ enc) {
    int b = blockIdx.x / SKK, s = blockIdx.x % SKK;
    int t = threadIdx.x, warp = t >> 5, lane = t & 31;
    __shared__ float se[DM];
    int l = (s * LK) / SKK;
    for (int j = t; j < DM; j += 256) se[j] = enc[((size_t)b * LK + l) * DM + j];
    __syncthreads();
    const float4* se4 = (const float4*)se;
    for (int row = warp; row < ROWS; row += 8) {
        const float4* qw4 = (const float4*)(g_qw + row * DM);
        float a = 0.f;
        #pragma unroll
        for (int k = 0; k < 4; k++) {
            int idx = lane + k * 32;
            float4 q = qw4[idx], e = se4[idx];
            a += q.x * e.x + q.y * e.y + q.z * e.z + q.w * e.w;
        }
        #pragma unroll
        for (int o = 16; o; o >>= 1) a += __shfl_down_sync(0xffffffffu, a, o);
        if (lane == 0) g_sc[(b * ROWS + row) * 48 + s] = a;
    }
}

// ---------------- M = max-mean; stable top-20 mask ----------------
__global__ void samp_select() {
    __shared__ float sM[ROWS];
    int b = blockIdx.x, t = threadIdx.x;
    if (t < ROWS) {
        const float* sc = g_sc + (b * ROWS + t) * 48;
        float mx = -1e30f, su = 0.f;
        for (int s = 0; s < SKK; s++) { float v = sc[s]; mx = fmaxf(mx, v); su += v; }
        sM[t] = mx - su * (1.0f / SKK);
    }
    __syncthreads();
    if (t < ROWS) {
        int h = t / LQ, q = t % LQ, base = h * LQ, rank = 0;
        float mv = sM[t];
        for (int i = 0; i < LQ; i++) {
            float o = sM[base + i];
            rank += (o > mv) || (o == mv && i < q);
        }
        g_istop[b * ROWS + t] = (rank < NTOP) ? 1 : 0;
    }
}

// ---------------- S GEMM (fp16): P = exp(0.125*qW@enc^T). k-chunk 64 --------
#define SHSTG 16128  // halfs per stage: A 96*72 + B 128*72
__global__ void __launch_bounds__(256) s_gemm(int dummy) {
    extern __shared__ __align__(16) char smraw[];
    int t = threadIdx.x, warp = t >> 5;
    int nt = blockIdx.x, mt = blockIdx.y, b = blockIdx.z;
    int m0 = mt * 96, n0 = nt * 128;
    int wm = warp >> 2, wn = warp & 3;
    const __half* Ag = g_qwh + (size_t)m0 * DM;
    const __half* Bg = g_ench + ((size_t)b * LK + n0) * DM;

    auto loadStage = [&](int st, int k0) {
        __half* As = (__half*)smraw + st * SHSTG;
        __half* Bs = As + 6912;
        #pragma unroll
        for (int i4 = t; i4 < 768; i4 += 256) {
            int r = i4 >> 3, c8 = (i4 & 7) * 8;
            cp16(As + r * 72 + c8, Ag + (size_t)r * DM + k0 + c8);
        }
        #pragma unroll
        for (int i4 = t; i4 < 1024; i4 += 256) {
            int l = i4 >> 3, c8 = (i4 & 7) * 8;
            cp16(Bs + l * 72 + c8, Bg + (size_t)l * DM + k0 + c8);
        }
        cp_commit();
    };

    wmma::fragment<wmma::accumulator, 16, 16, 16, float> acc[3][2];
    #pragma unroll
    for (int i = 0; i < 3; i++)
        #pragma unroll
        for (int j = 0; j < 2; j++) wmma::fill_fragment(acc[i][j], 0.0f);

    loadStage(0, 0);
    loadStage(1, 64);
    for (int ks = 0; ks < 8; ks++) {
        if (ks < 7) cp_wait<1>(); else cp_wait<0>();
        __syncthreads();
        if (ks + 2 < 8) loadStage((ks + 2) % 3, (ks + 2) * 64);
        __half* As = (__half*)smraw + (ks % 3) * SHSTG;
        __half* Bs = As + 6912;
        #pragma unroll
        for (int kk = 0; kk < 4; kk++) {
            wmma::fragment<wmma::matrix_a, 16, 16, 16, __half, wmma::row_major> af[3];
            wmma::fragment<wmma::matrix_b, 16, 16, 16, __half, wmma::col_major> bf[2];
            #pragma unroll
            for (int i = 0; i < 3; i++)
                wmma::load_matrix_sync(af[i], As + (wm * 48 + i * 16) * 72 + kk * 16, 72);
            #pragma unroll
            for (int j = 0; j < 2; j++)
                wmma::load_matrix_sync(bf[j], Bs + (wn * 32 + j * 16) * 72 + kk * 16, 72);
            #pragma unroll
            for (int i = 0; i < 3; i++)
                #pragma unroll
                for (int j = 0; j < 2; j++) wmma::mma_sync(acc[i][j], af[i], bf[j], acc[i][j]);
        }
    }
    __syncthreads();
    float* Ss = (float*)smraw;  // [96][132]
    #pragma unroll
    for (int i = 0; i < 3; i++)
        #pragma unroll
        for (int j = 0; j < 2; j++)
            wmma::store_matrix_sync(Ss + (wm * 48 + i * 16) * 132 + wn * 32 + j * 16,
                                    acc[i][j], 132, wmma::mem_row_major);
    __syncthreads();
    size_t base = ((size_t)b * RPAD + m0) * LK + n0;
    for (int i4 = t; i4 < 3072; i4 += 256) {
        int r = i4 >> 5, c4 = (i4 & 31) * 4;
        float4 v = *(float4*)(Ss + r * 132 + c4);
        v.x = __expf(v.x * 0.125f); v.y = __expf(v.y * 0.125f);
        v.z = __expf(v.z * 0.125f); v.w = __expf(v.w * 0.125f);
        *(float4*)(Ss + r * 132 + c4) = v;
        __half h4[4];
        h4[0] = __float2half_rn(v.x); h4[1] = __float2half_rn(v.y);
        h4[2] = __float2half_rn(v.z); h4[3] = __float2half_rn(v.w);
        *(uint2*)(g_Sh + base + (size_t)r * LK + c4) = *(uint2*)h4;
    }
    __syncthreads();
    if (t < 96) {
        float su = 0.f;
        for (int c = 0; c < 128; c++) su += Ss[t * 132 + c];
        g_psum[(b * RPAD + m0 + t) * 32 + nt] = su;
    }
}

// ---------------- merge row sums ----------------
__global__ void stat_merge() {
    int r = blockIdx.x * 256 + threadIdx.x;
    if (r >= NB * RPAD) return;
    float s = 0.f;
    for (int i = 0; i < 32; i++) s += g_psum[r * 32 + i];
    g_rinv[r] = 1.0f / s;
}

// ---------------- u GEMM (fp16): u = P @ enc, kc=4 split, k-chunk 64 ---------
#define UHSTG 15616  // halfs per stage: A 96*72 + B 64*136
__global__ void __launch_bounds__(256) u_gemm(int dummy) {
    extern __shared__ __align__(16) char smraw[];
    int t = threadIdx.x, warp = t >> 5;
    int gx = blockIdx.x, b = blockIdx.y;
    int nt = gx & 3, mt = (gx >> 2) & 1, kc = gx >> 3;
    int m0 = mt * 96, n0 = nt * 128;
    int wm = warp >> 2, wn = warp & 3;
    const __half* Ag = g_Sh + ((size_t)b * RPAD + m0) * LK + kc * 1024;
    const __half* Bg = g_ench + ((size_t)b * LK + kc * 1024) * DM + n0;

    auto loadStage = [&](int st, int k0) {
        __half* As = (__half*)smraw + st * UHSTG;
        __half* Bs = As + 6912;
        #pragma unroll
        for (int i4 = t; i4 < 768; i4 += 256) {
            int r = i4 >> 3, c8 = (i4 & 7) * 8;
            cp16(As + r * 72 + c8, Ag + (size_t)r * LK + k0 + c8);
        }
        #pragma unroll
        for (int i4 = t; i4 < 1024; i4 += 256) {
            int l = i4 >> 4, c8 = (i4 & 15) * 8;
            cp16(Bs + l * 136 + c8, Bg + (size_t)(k0 + l) * DM + c8);
        }
        cp_commit();
    };

    wmma::fragment<wmma::accumulator, 16, 16, 16, float> acc[3][2];
    #pragma unroll
    for (int i = 0; i < 3; i++)
        #pragma unroll
        for (int j = 0; j < 2; j++) wmma::fill_fragment(acc[i][j], 0.0f);

    loadStage(0, 0);
    loadStage(1, 64);
    for (int ks = 0; ks < 16; ks++) {
        if (ks < 15) cp_wait<1>(); else cp_wait<0>();
        __syncthreads();
        if (ks + 2 < 16) loadStage((ks + 2) % 3, (ks + 2) * 64);
        __half* As = (__half*)smraw + (ks % 3) * UHSTG;
        __half* Bs = As + 6912;
        #pragma unroll
        for (int kk = 0; kk < 4; kk++) {
            wmma::fragment<wmma::matrix_a, 16, 16, 16, __half, wmma::row_major> af[3];
            wmma::fragment<wmma::matrix_b, 16, 16, 16, __half, wmma::row_major> bf[2];
            #pragma unroll
            for (int i = 0; i < 3; i++)
                wmma::load_matrix_sync(af[i], As + (wm * 48 + i * 16) * 72 + kk * 16, 72);
            #pragma unroll
            for (int j = 0; j < 2; j++)
                wmma::load_matrix_sync(bf[j], Bs + (kk * 16) * 136 + wn * 32 + j * 16, 136);
            #pragma unroll
            for (int i = 0; i < 3; i++)
                #pragma unroll
                for (int j = 0; j < 2; j++) wmma::mma_sync(acc[i][j], af[i], bf[j], acc[i][j]);
        }
    }
    __syncthreads();
    float* Ss = (float*)smraw;  // [96][132]
    #pragma unroll
    for (int i = 0; i < 3; i++)
        #pragma unroll
        for (int j = 0; j < 2; j++)
            wmma::store_matrix_sync(Ss + (wm * 48 + i * 16) * 132 + wn * 32 + j * 16,
                                    acc[i][j], 132, wmma::mem_row_major);
    __syncthreads();
    __half* up = g_uh + (size_t)kc * NB * RPAD * DM + ((size_t)(b * RPAD + m0)) * DM + n0;
    for (int i4 = t; i4 < 3072; i4 += 256) {
        int r = i4 >> 5, c4 = (i4 & 31) * 4;
        float4 v = *(float4*)(Ss + r * 132 + c4);
        __half h4[4];
        h4[0] = __float2half_rn(v.x); h4[1] = __float2half_rn(v.y);
        h4[2] = __float2half_rn(v.z); h4[3] = __float2half_rn(v.w);
        *(uint2*)(up + (size_t)r * DM + c4) = *(uint2*)h4;
    }
}

// ---------------- ctx: top rows (u*rinv)@Wv_h + bv, else v-mean --------------
__global__ void ctx_kernel(const float* __restrict__ Wv, const float* __restrict__ bv) {
    __shared__ float su[LQ * DM];
    __shared__ float svm[64];
    int bh = blockIdx.x, b = bh >> 3, h = bh & 7, t = threadIdx.x;
    const size_t ub = ((size_t)b * RPAD + h * LQ) * DM;
    const size_t part = (size_t)NB * RPAD * DM;
    for (int i = t; i < LQ * DM; i += 256) {
        int q = i >> 9;
        float s = __half2float(g_uh[ub + i]) + __half2float(g_uh[part + ub + i])
                + __half2float(g_uh[2 * part + ub + i]) + __half2float(g_uh[3 * part + ub + i]);
        su[i] = s * g_rinv[b * RPAD + h * LQ + q];
    }
    if (t < 64) {
        float a = bv[h * 64 + t];
        const float inv = 1.0f / 4096.f;
        for (int c = 0; c < DM; c++) a += g_encsum[b * DM + c] * inv * Wv[c * DM + h * 64 + t];
        svm[t] = a;
    }
    __syncthreads();
    for (int i = t; i < LQ * 64; i += 256) {
        int q = i >> 6, d = i & 63;
        float v;
        if (g_istop[b * ROWS + h * LQ + q]) {
            float a = bv[h * 64 + d];
            for (int c = 0; c < DM; c++) a += su[q * DM + c] * Wv[c * DM + h * 64 + d];
            v = a;
        } else v = svm[d];
        g_ctx[((size_t)b * LQ + q) * DM + h * 64 + d] = v;
    }
}

// ---------------- o GEMM (tf32): g_ao = 2*(ctx @ Wo + bo), 3-stage -----------
#define OSTG 7680  // floats per stage: As 96*36 + Bs 32*132
__global__ void __launch_bounds__(256) o_gemm(const float* __restrict__ Wo,
                                              const float* __restrict__ bo) {
    extern __shared__ __align__(16) char smraw[];
    float* smd = (float*)smraw;
    int t = threadIdx.x, warp = t >> 5;
    int m0 = blockIdx.y * 96, n0 = blockIdx.x * 128;
    int wm = warp >> 2, wn = warp & 3;
    const float* Ag = g_ctx + (size_t)m0 * DM;
    const float* Bg = Wo + n0;

    auto loadStage = [&](int st, int k0) {
        float* As = smd + st * OSTG;
        float* Bs = As + 3456;
        #pragma unroll
        for (int i4 = t; i4 < 768; i4 += 256) {
            int r = i4 >> 3, c4 = (i4 & 7) * 4;
            cp16(As + r * 36 + c4, Ag + (size_t)r * DM + k0 + c4);
        }
        #pragma unroll
        for (int i4 = t; i4 < 1024; i4 += 256) {
            int l = i4 >> 5, c4 = (i4 & 31) * 4;
            cp16(Bs + l * 132 + c4, Bg + (size_t)(k0 + l) * DM + c4);
        }
        cp_commit();
    };

    wmma::fragment<wmma::accumulator, 16, 16, 8, float> acc[3][2];
    #pragma unroll
    for (int i = 0; i < 3; i++)
        #pragma unroll
        for (int j = 0; j < 2; j++) wmma::fill_fragment(acc[i][j], 0.0f);

    loadStage(0, 0);
    loadStage(1, 32);
    for (int ks = 0; ks < 16; ks++) {
        if (ks < 15) cp_wait<1>(); else cp_wait<0>();
        __syncthreads();
        if (ks + 2 < 16) loadStage((ks + 2) % 3, (ks + 2) * 32);
        float* As = smd + (ks % 3) * OSTG;
        float* Bs = As + 3456;
        #pragma unroll
        for (int kk = 0; kk < 4; kk++) {
            wmma::fragment<wmma::matrix_a, 16, 16, 8, wmma::precision::tf32, wmma::row_major> af[3];
            wmma::fragment<wmma::matrix_b, 16, 16, 8, wmma::precision::tf32, wmma::row_major> bf[2];
            #pragma unroll
            for (int i = 0; i < 3; i++) {
                wmma::load_matrix_sync(af[i], As + (wm * 48 + i * 16) * 36 + kk * 8, 36);
                #pragma unroll
                for (int e = 0; e < af[i].num_elements; e++) af[i].x[e] = wmma::__float_to_tf32(af[i].x[e]);
            }
            #pragma unroll
            for (int j = 0; j < 2; j++) {
                wmma::load_matrix_sync(bf[j], Bs + (kk * 8) * 132 + wn * 32 + j * 16, 132);
                #pragma unroll
                for (int e = 0; e < bf[j].num_elements; e++) bf[j].x[e] = wmma::__float_to_tf32(bf[j].x[e]);
            }
            #pragma unroll
            for (int i = 0; i < 3; i++)
                #pragma unroll
                for (int j = 0; j < 2; j++) wmma::mma_sync(acc[i][j], af[i], bf[j], acc[i][j]);
        }
    }
    __syncthreads();
    float* Ss = smd;
    #pragma unroll
    for (int i = 0; i < 3; i++)
        #pragma unroll
        for (int j = 0; j < 2; j++)
            wmma::store_matrix_sync(Ss + (wm * 48 + i * 16) * 132 + wn * 32 + j * 16,
                                    acc[i][j], 132, wmma::mem_row_major);
    __syncthreads();
    for (int i4 = t; i4 < 3072; i4 += 256) {
        int r = i4 >> 5, c4 = (i4 & 31) * 4;
        int row = m0 + r, n = n0 + c4;
        if (row >= MROWS) continue;
        float4 v = *(float4*)(Ss + r * 132 + c4);
        v.x = 2.0f * (v.x + bo[n + 0]); v.y = 2.0f * (v.y + bo[n + 1]);
        v.z = 2.0f * (v.z + bo[n + 2]); v.w = 2.0f * (v.w + bo[n + 3]);
        *(float4*)(g_ao + (size_t)row * DM + n) = v;
    }
}

// ---------------- ln1: x = LN(g_ao) (fp32 + fp16) ----------------
__global__ void ln1_kernel(const float* __restrict__ g1, const float* __restrict__ be1) {
    int r = blockIdx.x, t = threadIdx.x;
    __shared__ float red[32];
    float z0 = g_ao[(size_t)r * DM + t];
    float z1 = g_ao[(size_t)r * DM + t + 256];
    float s1 = blockReduce(z0 + z1, red);
    float s2 = blockReduce(z0 * z0 + z1 * z1, red);
    float mu = s1 * (1.0f / 512.f);
    float va = fmaxf(s2 * (1.0f / 512.f) - mu * mu, 0.f);
    float rs = rsqrtf(va + 1e-5f);
    float x0 = (z0 - mu) * rs * g1[t] + be1[t];
    float x1 = (z1 - mu) * rs * g1[t + 256] + be1[t + 256];
    g_x[(size_t)r * DM + t] = x0;
    g_x[(size_t)r * DM + t + 256] = x1;
    g_xh[(size_t)r * DM + t] = __float2half_rn(x0);
    g_xh[(size_t)r * DM + t + 256] = __float2half_rn(x1);
}

// ---------------- ffn1 (fp16): g_ffh = relu(x @ w1^T + b1), k-chunk 64 -------
__global__ void __launch_bounds__(256) ffn1_gemm(const float* __restrict__ b1) {
    extern __shared__ __align__(16) char smraw[];
    int t = threadIdx.x, warp = t >> 5;
    int m0 = blockIdx.y * 96, n0 = blockIdx.x * 128;
    int wm = warp >> 2, wn = warp & 3;
    const __half* Ag = g_xh + (size_t)m0 * DM;
    const __half* Bg = g_w1h + (size_t)n0 * DM;

    auto loadStage = [&](int st, int k0) {
        __half* As = (__half*)smraw + st * SHSTG;
        __half* Bs = As + 6912;
        #pragma unroll
        for (int i4 = t; i4 < 768; i4 += 256) {
            int r = i4 >> 3, c8 = (i4 & 7) * 8;
            cp16(As + r * 72 + c8, Ag + (size_t)r * DM + k0 + c8);
        }
        #pragma unroll
        for (int i4 = t; i4 < 1024; i4 += 256) {
            int n = i4 >> 3, c8 = (i4 & 7) * 8;
            cp16(Bs + n * 72 + c8, Bg + (size_t)n * DM + k0 + c8);
        }
        cp_commit();
    };

    wmma::fragment<wmma::accumulator, 16, 16, 16, float> acc[3][2];
    #pragma unroll
    for (int i = 0; i < 3; i++)
        #pragma unroll
        for (int j = 0; j < 2; j++) wmma::fill_fragment(acc[i][j], 0.0f);

    loadStage(0, 0);
    loadStage(1, 64);
    for (int ks = 0; ks < 8; ks++) {
        if (ks < 7) cp_wait<1>(); else cp_wait<0>();
        __syncthreads();
        if (ks + 2 < 8) loadStage((ks + 2) % 3, (ks + 2) * 64);
        __half* As = (__half*)smraw + (ks % 3) * SHSTG;
        __half* Bs = As + 6912;
        #pragma unroll
        for (int kk = 0; kk < 4; kk++) {
            wmma::fragment<wmma::matrix_a, 16, 16, 16, __half, wmma::row_major> af[3];
            wmma::fragment<wmma::matrix_b, 16, 16, 16, __half, wmma::col_major> bf[2];
            #pragma unroll
            for (int i = 0; i < 3; i++)
                wmma::load_matrix_sync(af[i], As + (wm * 48 + i * 16) * 72 + kk * 16, 72);
            #pragma unroll
            for (int j = 0; j < 2; j++)
                wmma::load_matrix_sync(bf[j], Bs + (wn * 32 + j * 16) * 72 + kk * 16, 72);
            #pragma unroll
            for (int i = 0; i < 3; i++)
                #pragma unroll
                for (int j = 0; j < 2; j++) wmma::mma_sync(acc[i][j], af[i], bf[j], acc[i][j]);
        }
    }
    __syncthreads();
    float* Ss = (float*)smraw;
    #pragma unroll
    for (int i = 0; i < 3; i++)
        #pragma unroll
        for (int j = 0; j < 2; j++)
            wmma::store_matrix_sync(Ss + (wm * 48 + i * 16) * 132 + wn * 32 + j * 16,
                                    acc[i][j], 132, wmma::mem_row_major);
    __syncthreads();
    for (int i4 = t; i4 < 3072; i4 += 256) {
        int r = i4 >> 5, c4 = (i4 & 31) * 4;
        int row = m0 + r, n = n0 + c4;
        if (row >= MROWS) continue;
        float4 v = *(float4*)(Ss + r * 132 + c4);
        __half h4[4];
        h4[0] = __float2half_rn(fmaxf(v.x + b1[n + 0], 0.f));
        h4[1] = __float2half_rn(fmaxf(v.y + b1[n + 1], 0.f));
        h4[2] = __float2half_rn(fmaxf(v.z + b1[n + 2], 0.f));
        h4[3] = __float2half_rn(fmaxf(v.w + b1[n + 3], 0.f));
        *(uint2*)(g_ffh + (size_t)row * DFF + n) = *(uint2*)h4;
    }
}

// ---------------- ffn2 (fp16): g_zp[kc] = ff[:,kc]@w2[:,kc]^T, k-chunk 64 ----
__global__ void __launch_bounds__(256) ffn2_gemm(int dummy) {
    extern __shared__ __align__(16) char smraw[];
    int t = threadIdx.x, warp = t >> 5;
    int m0 = blockIdx.y * 96, n0 = blockIdx.x * 128, kc = blockIdx.z;
    int wm = warp >> 2, wn = warp & 3;
    const __half* Ag = g_ffh + (size_t)m0 * DFF + kc * 512;
    const __half* Bg = g_w2h + (size_t)n0 * DFF + kc * 512;

    auto loadStage = [&](int st, int k0) {
        __half* As = (__half*)smraw + st * SHSTG;
        __half* Bs = As + 6912;
        #pragma unroll
        for (int i4 = t; i4 < 768; i4 += 256) {
            int r = i4 >> 3, c8 = (i4 & 7) * 8;
            cp16(As + r * 72 + c8, Ag + (size_t)r * DFF + k0 + c8);
        }
        #pragma unroll
        for (int i4 = t; i4 < 1024; i4 += 256) {
            int n = i4 >> 3, c8 = (i4 & 7) * 8;
            cp16(Bs + n * 72 + c8, Bg + (size_t)n * DFF + k0 + c8);
        }
        cp_commit();
    };

    wmma::fragment<wmma::accumulator, 16, 16, 16, float> acc[3][2];
    #pragma unroll
    for (int i = 0; i < 3; i++)
        #pragma unroll
        for (int j = 0; j < 2; j++) wmma::fill_fragment(acc[i][j], 0.0f);

    loadStage(0, 0);
    loadStage(1, 64);
    for (int ks = 0; ks < 8; ks++) {
        if (ks < 7) cp_wait<1>(); else cp_wait<0>();
        __syncthreads();
        if (ks + 2 < 8) loadStage((ks + 2) % 3, (ks + 2) * 64);
        __half* As = (__half*)smraw + (ks % 3) * SHSTG;
        __half* Bs = As + 6912;
        #pragma unroll
        for (int kk = 0; kk < 4; kk++) {
            wmma::fragment<wmma::matrix_a, 16, 16, 16, __half, wmma::row_major> af[3];
            wmma::fragment<wmma::matrix_b, 16, 16, 16, __half, wmma::col_major> bf[2];
            #pragma unroll
            for (int i = 0; i < 3; i++)
                wmma::load_matrix_sync(af[i], As + (wm * 48 + i * 16) * 72 + kk * 16, 72);
            #pragma unroll
            for (int j = 0; j < 2; j++)
                wmma::load_matrix_sync(bf[j], Bs + (wn * 32 + j * 16) * 72 + kk * 16, 72);
            #pragma unroll
            for (int i = 0; i < 3; i++)
                #pragma unroll
                for (int j = 0; j < 2; j++) wmma::mma_sync(acc[i][j], af[i], bf[j], acc[i][j]);
        }
    }
    __syncthreads();
    float* Ss = (float*)smraw;
    #pragma unroll
    for (int i = 0; i < 3; i++)
        #pragma unroll
        for (int j = 0; j < 2; j++)
            wmma::store_matrix_sync(Ss + (wm * 48 + i * 16) * 132 + wn * 32 + j * 16,
                                    acc[i][j], 132, wmma::mem_row_major);
    __syncthreads();
    float* Cp = g_zp + (size_t)kc * MROWS * DM;
    for (int i4 = t; i4 < 3072; i4 += 256) {
        int r = i4 >> 5, c4 = (i4 & 31) * 4;
        int row = m0 + r, n = n0 + c4;
        if (row >= MROWS) continue;
        *(float4*)(Cp + (size_t)row * DM + n) = *(float4*)(Ss + r * 132 + c4);
    }
}

// ---------------- f3b: z = x + b2 + sum partials; y = LN(z); forecast --------
__global__ void f3b_kernel(const float* __restrict__ b2,
                           const float* __restrict__ g2, const float* __restrict__ be2,
                           const float* __restrict__ Wout, const float* __restrict__ bout,
                           float* __restrict__ out) {
    int r = blockIdx.x, t = threadIdx.x;
    __shared__ float red[32];
    const size_t part = (size_t)MROWS * DM;
    size_t o0 = (size_t)r * DM + t, o1 = o0 + 256;
    float z0 = g_x[o0] + b2[t] + g_zp[o0] + g_zp[part + o0] + g_zp[2 * part + o0] + g_zp[3 * part + o0];
    float z1 = g_x[o1] + b2[t + 256] + g_zp[o1] + g_zp[part + o1] + g_zp[2 * part + o1] + g_zp[3 * part + o1];
    float s1 = blockReduce(z0 + z1, red);
    float s2 = blockReduce(z0 * z0 + z1 * z1, red);
    float mu = s1 * (1.0f / 512.f);
    float va = fmaxf(s2 * (1.0f / 512.f) - mu * mu, 0.f);
    float rs = rsqrtf(va + 1e-5f);
    float y0 = (z0 - mu) * rs * g2[t] + be2[t];
    float y1 = (z1 - mu) * rs * g2[t + 256] + be2[t + 256];
    out[NB * LQ + (size_t)r * DM + t] = y0;
    out[NB * LQ + (size_t)r * DM + t + 256] = y1;
    float f = blockReduce(y0 * Wout[t] + y1 * Wout[t + 256], red);
    if (t == 0) out[r] = f + bout[0];
}

// ---------------- launch ----------------
extern "C" void kernel_launch(void* const* d_in, const int* in_sizes, int n_in,
                              void* d_out, int out_size) {
    const float* enc  = (const float*)d_in[0];
    const float* Wq   = (const float*)d_in[1];
    const float* bq   = (const float*)d_in[2];
    const float* Wk   = (const float*)d_in[3];
    const float* Wv   = (const float*)d_in[5];
    const float* bv   = (const float*)d_in[6];
    const float* Wo   = (const float*)d_in[7];
    const float* bo   = (const float*)d_in[8];
    const float* w1   = (const float*)d_in[9];
    const float* b1   = (const float*)d_in[10];
    const float* w2   = (const float*)d_in[11];
    const float* b2   = (const float*)d_in[12];
    const float* g1   = (const float*)d_in[13];
    const float* be1  = (const float*)d_in[14];
    const float* g2   = (const float*)d_in[15];
    const float* be2  = (const float*)d_in[16];
    const float* Wout = (const float*)d_in[17];
    const float* bout = (const float*)d_in[18];
    float* out = (float*)d_out;

    cudaFuncSetAttribute(s_gemm,    cudaFuncAttributeMaxDynamicSharedMemorySize, 3 * SHSTG * 2);
    cudaFuncSetAttribute(u_gemm,    cudaFuncAttributeMaxDynamicSharedMemorySize, 3 * UHSTG * 2);
    cudaFuncSetAttribute(o_gemm,    cudaFuncAttributeMaxDynamicSharedMemorySize, 3 * OSTG * 4);
    cudaFuncSetAttribute(ffn1_gemm, cudaFuncAttributeMaxDynamicSharedMemorySize, 3 * SHSTG * 2);
    cudaFuncSetAttribute(ffn2_gemm, cudaFuncAttributeMaxDynamicSharedMemorySize, 3 * SHSTG * 2);

    q_kernel<<<22, 256>>>(Wq, bq);                                // 1 (+zero encsum)
    qw_kernel<<<176, 256>>>(Wk);                                  // 2
    dim3 gcv(LK / 64, NB);
    enc_cvt<<<gcv, 256>>>(enc);                                   // 3
    dim3 gc(32, 2, NB);
    s_gemm<<<gc, 256, 3 * SHSTG * 2>>>(0);                        // 4  <- ncu slot
    wcvt<<<DFF * DM / 1024, 256>>>(w1, w2);                       // 5
    samp_score<<<NB * SKK, 256>>>(enc);                           // 6
    samp_select<<<NB, 256>>>();                                   // 7
    stat_merge<<<24, 256>>>();                                    // 8
    dim3 ge(32, NB);
    u_gemm<<<ge, 256, 3 * UHSTG * 2>>>(0);                        // 9
    ctx_kernel<<<256, 256>>>(Wv, bv);                             // 10
    dim3 go(4, 8);
    o_gemm<<<go, 256, 3 * OSTG * 4>>>(Wo, bo);                    // 11
    ln1_kernel<<<MROWS, 256>>>(g1, be1);                          // 12
    dim3 gf1(16, 8);
    ffn1_gemm<<<gf1, 256, 3 * SHSTG * 2>>>(b1);                   // 13
    dim3 gf2(4, 8, 4);
    ffn2_gemm<<<gf2, 256, 3 * SHSTG * 2>>>(0);                    // 14
    f3b_kernel<<<MROWS, 256>>>(b2, g2, be2, Wout, bout, out);     // 15
}